// round 3
// baseline (speedup 1.0000x reference)
#include <cuda_runtime.h>
#include <cuda_fp16.h>
#include <mma.h>

using namespace nvcuda;

// Problem constants
#define B_ 4
#define L_ 2048
#define D_ 1024
#define H_ 16
#define HD_ 64
#define MROWS 8192      // B*L
#define N3D 3072        // 3*D

// ---------------- device scratch (static allocation only) ----------------
__device__ __align__(16) __half g_xh[MROWS * D_];
__device__ __align__(16) __half g_xl[MROWS * D_];
__device__ __align__(16) __half g_wqh[D_ * N3D];
__device__ __align__(16) __half g_wql[D_ * N3D];
__device__ __align__(16) __half g_woh[D_ * D_];
__device__ __align__(16) __half g_wol[D_ * D_];
__device__ __align__(16) float  g_qkv[(size_t)MROWS * N3D];
__device__ __align__(16) __half g_q_hi[64 * 2048 * 64];
__device__ __align__(16) __half g_q_lo[64 * 2048 * 64];
__device__ __align__(16) __half g_k_hi[64 * 2048 * 64];
__device__ __align__(16) __half g_k_lo[64 * 2048 * 64];
__device__ __align__(16) __half g_v_hi[64 * 2048 * 64];
__device__ __align__(16) __half g_v_lo[64 * 2048 * 64];
__device__ __align__(16) __half g_aoh[MROWS * D_];
__device__ __align__(16) __half g_aol[MROWS * D_];
__device__ __align__(16) float  g_cos[L_ * 32];
__device__ __align__(16) float  g_sin[L_ * 32];

// ---------------- fp32 -> (hi,lo) half split ----------------
__global__ void k_split(const float* __restrict__ src, int which, int n4) {
    __half* hi;
    __half* lo;
    if (which == 0)      { hi = g_xh;  lo = g_xl;  }
    else if (which == 1) { hi = g_wqh; lo = g_wql; }
    else                 { hi = g_woh; lo = g_wol; }
    int i = blockIdx.x * blockDim.x + threadIdx.x;
    if (i >= n4) return;
    float4 v = reinterpret_cast<const float4*>(src)[i];
    __half h0 = __float2half(v.x), h1 = __float2half(v.y);
    __half h2 = __float2half(v.z), h3 = __float2half(v.w);
    __half l0 = __float2half(v.x - __half2float(h0));
    __half l1 = __float2half(v.y - __half2float(h1));
    __half l2 = __float2half(v.z - __half2float(h2));
    __half l3 = __float2half(v.w - __half2float(h3));
    reinterpret_cast<__half2*>(hi)[2 * i]     = __halves2half2(h0, h1);
    reinterpret_cast<__half2*>(hi)[2 * i + 1] = __halves2half2(h2, h3);
    reinterpret_cast<__half2*>(lo)[2 * i]     = __halves2half2(l0, l1);
    reinterpret_cast<__half2*>(lo)[2 * i + 1] = __halves2half2(l2, l3);
}

// ---------------- RoPE cos/sin table (double-precision reduction) ----------------
__global__ void k_rope_tab() {
    int i = blockIdx.x * blockDim.x + threadIdx.x;
    if (i >= L_ * 32) return;
    int l = i >> 5, f = i & 31;
    double invd = pow(10000.0, -(double)(2 * f) / 64.0);
    float invf = (float)invd;             // fp32 inv_freq (matches jax fp32 value ~1ulp)
    float ang = (float)l * invf;          // fp32 angle, matches reference rounding
    double da = (double)ang;
    g_cos[i] = (float)cos(da);
    g_sin[i] = (float)sin(da);
}

// ---------------- split-fp16 WMMA GEMM: C = (Ah+Al)(Bh+Bl) + bias ----------------
// which==0: A=x(split), B=Wqkv(split), C=g_qkv       (M=8192,N=3072,K=1024)
// which==1: A=attn_out(split), B=Wout(split), C=Cext (M=8192,N=1024,K=1024)
__global__ __launch_bounds__(256) void k_gemm(int which, const float* __restrict__ bias,
                                              float* __restrict__ Cext,
                                              int M, int N, int K) {
    const __half* Ah = which ? g_aoh : g_xh;
    const __half* Al = which ? g_aol : g_xl;
    const __half* Bh = which ? g_woh : g_wqh;
    const __half* Bl = which ? g_wol : g_wql;
    float* C = which ? Cext : g_qkv;

    constexpr int BK = 32;
    __shared__ __align__(32) __half Ash[128][BK + 8];
    __shared__ __align__(32) __half Asl[128][BK + 8];
    __shared__ __align__(32) __half Bsh[BK][128 + 8];
    __shared__ __align__(32) __half Bsl[BK][128 + 8];
    __shared__ __align__(32) float  stag[8][256];

    int tid = threadIdx.x;
    int m0 = blockIdx.y * 128, n0 = blockIdx.x * 128;
    int wid = tid >> 5, lane = tid & 31;
    int wm = wid & 3, wn = wid >> 2;   // 4x2 warp grid; warp tile 32x64

    wmma::fragment<wmma::accumulator, 16, 16, 16, float> acc[2][4];
#pragma unroll
    for (int mi = 0; mi < 2; mi++)
#pragma unroll
        for (int ni = 0; ni < 4; ni++) wmma::fill_fragment(acc[mi][ni], 0.0f);

    for (int k0 = 0; k0 < K; k0 += BK) {
#pragma unroll
        for (int s = 0; s < 2; s++) {
            int v = tid + s * 256;
            int r = v >> 2, c = (v & 3) * 8;
            *reinterpret_cast<int4*>(&Ash[r][c]) =
                *reinterpret_cast<const int4*>(&Ah[(size_t)(m0 + r) * K + k0 + c]);
            *reinterpret_cast<int4*>(&Asl[r][c]) =
                *reinterpret_cast<const int4*>(&Al[(size_t)(m0 + r) * K + k0 + c]);
        }
#pragma unroll
        for (int s = 0; s < 2; s++) {
            int v = tid + s * 256;
            int r = v >> 4, c = (v & 15) * 8;
            *reinterpret_cast<int4*>(&Bsh[r][c]) =
                *reinterpret_cast<const int4*>(&Bh[(size_t)(k0 + r) * N + n0 + c]);
            *reinterpret_cast<int4*>(&Bsl[r][c]) =
                *reinterpret_cast<const int4*>(&Bl[(size_t)(k0 + r) * N + n0 + c]);
        }
        __syncthreads();

#pragma unroll
        for (int kk = 0; kk < BK; kk += 16) {
            wmma::fragment<wmma::matrix_a, 16, 16, 16, __half, wmma::row_major> ah[2], al[2];
#pragma unroll
            for (int mi = 0; mi < 2; mi++) {
                wmma::load_matrix_sync(ah[mi], &Ash[wm * 32 + mi * 16][kk], BK + 8);
                wmma::load_matrix_sync(al[mi], &Asl[wm * 32 + mi * 16][kk], BK + 8);
            }
#pragma unroll
            for (int ni = 0; ni < 4; ni++) {
                wmma::fragment<wmma::matrix_b, 16, 16, 16, __half, wmma::row_major> bh, bl;
                wmma::load_matrix_sync(bh, &Bsh[kk][wn * 64 + ni * 16], 128 + 8);
                wmma::load_matrix_sync(bl, &Bsl[kk][wn * 64 + ni * 16], 128 + 8);
#pragma unroll
                for (int mi = 0; mi < 2; mi++) {
                    wmma::mma_sync(acc[mi][ni], ah[mi], bh, acc[mi][ni]);
                    wmma::mma_sync(acc[mi][ni], al[mi], bh, acc[mi][ni]);
                    wmma::mma_sync(acc[mi][ni], ah[mi], bl, acc[mi][ni]);
                }
            }
        }
        __syncthreads();
    }

    // epilogue: stage each 16x16 tile through smem, add bias, write fp32
#pragma unroll
    for (int mi = 0; mi < 2; mi++) {
#pragma unroll
        for (int ni = 0; ni < 4; ni++) {
            wmma::store_matrix_sync(&stag[wid][0], acc[mi][ni], 16, wmma::mem_row_major);
            __syncwarp();
            int r = lane >> 1, c0 = (lane & 1) * 8;
            int gr = m0 + wm * 32 + mi * 16 + r;
            int gc = n0 + wn * 64 + ni * 16 + c0;
#pragma unroll
            for (int j = 0; j < 8; j++)
                C[(size_t)gr * N + gc + j] = stag[wid][r * 16 + c0 + j] + bias[gc + j];
            __syncwarp();
        }
    }
}

// ---------------- RMSNorm + RoPE + scale, layout to [bh][l][hd], split ----------------
__global__ __launch_bounds__(256) void k_normrope(const float* __restrict__ qn_w,
                                                  const float* __restrict__ kn_w) {
    int gw = blockIdx.x * 8 + (threadIdx.x >> 5);  // global warp id: 8192*16
    int lane = threadIdx.x & 31;
    int r = gw >> 4;     // row in [0,8192)
    int h = gw & 15;
    int b = r >> 11;
    int l = r & 2047;
    const float* row = &g_qkv[(size_t)r * N3D];
    float cv = g_cos[l * 32 + lane];
    float sv = g_sin[l * 32 + lane];
    int dst = ((b * 16 + h) * 2048 + l) * 64 + lane;

    // Q: rmsnorm + rope + fold scale 1/sqrt(HD)=0.125
    {
        float t1 = row[h * 64 + lane];
        float t2 = row[h * 64 + lane + 32];
        float ss = t1 * t1 + t2 * t2;
#pragma unroll
        for (int o = 16; o > 0; o >>= 1) ss += __shfl_xor_sync(0xffffffffu, ss, o);
        float rms = rsqrtf(ss * (1.0f / 64.0f) + 1e-6f);
        t1 *= rms * qn_w[lane];
        t2 *= rms * qn_w[lane + 32];
        float o1 = (t1 * cv - t2 * sv) * 0.125f;
        float o2 = (t1 * sv + t2 * cv) * 0.125f;
        __half a = __float2half(o1);
        g_q_hi[dst] = a; g_q_lo[dst] = __float2half(o1 - __half2float(a));
        __half c = __float2half(o2);
        g_q_hi[dst + 32] = c; g_q_lo[dst + 32] = __float2half(o2 - __half2float(c));
    }
    // K: rmsnorm + rope
    {
        float t1 = row[1024 + h * 64 + lane];
        float t2 = row[1024 + h * 64 + lane + 32];
        float ss = t1 * t1 + t2 * t2;
#pragma unroll
        for (int o = 16; o > 0; o >>= 1) ss += __shfl_xor_sync(0xffffffffu, ss, o);
        float rms = rsqrtf(ss * (1.0f / 64.0f) + 1e-6f);
        t1 *= rms * kn_w[lane];
        t2 *= rms * kn_w[lane + 32];
        float o1 = t1 * cv - t2 * sv;
        float o2 = t1 * sv + t2 * cv;
        __half a = __float2half(o1);
        g_k_hi[dst] = a; g_k_lo[dst] = __float2half(o1 - __half2float(a));
        __half c = __float2half(o2);
        g_k_hi[dst + 32] = c; g_k_lo[dst + 32] = __float2half(o2 - __half2float(c));
    }
    // V: layout transform + split
    {
        float v1 = row[2048 + h * 64 + lane];
        float v2 = row[2048 + h * 64 + lane + 32];
        __half a = __float2half(v1);
        g_v_hi[dst] = a; g_v_lo[dst] = __float2half(v1 - __half2float(a));
        __half c = __float2half(v2);
        g_v_hi[dst + 32] = c; g_v_lo[dst + 32] = __float2half(v2 - __half2float(c));
    }
}

// ---------------- flash attention, split-fp16 WMMA, online softmax ----------------
// grid: (L/64, B*H); 256 threads; dynamic smem
__global__ __launch_bounds__(256) void k_attn() {
    extern __shared__ __align__(128) char sm[];
    const int LD = 72;
    __half* Qh = (__half*)(sm + 0);
    __half* Ql = (__half*)(sm + 9216);
    __half* Kh = (__half*)(sm + 18432);
    __half* Kl = (__half*)(sm + 27648);
    __half* Vh = (__half*)(sm + 36864);
    __half* Vl = (__half*)(sm + 46080);
    float*  Ss = (float*)(sm + 55296);   // 64x72 fp32, also holds PV result
    __half* Ph = (__half*)(sm + 73728);
    __half* Pl = (__half*)(sm + 82944);
    float*  mrow = (float*)(sm + 92160);
    float*  lrow = (float*)(sm + 92416);

    int tid = threadIdx.x;
    int wid = tid >> 5;
    int bh = blockIdx.y;
    int q0 = blockIdx.x * 64;
    size_t base = (size_t)bh * 2048 * 64;

    // load Q tile (64x64 hi/lo)
#pragma unroll
    for (int s = 0; s < 2; s++) {
        int v = tid + s * 256;
        int rr = v >> 3, c = (v & 7) * 8;
        size_t g = base + (size_t)(q0 + rr) * 64 + c;
        *reinterpret_cast<int4*>(&Qh[rr * LD + c]) = *reinterpret_cast<const int4*>(&g_q_hi[g]);
        *reinterpret_cast<int4*>(&Ql[rr * LD + c]) = *reinterpret_cast<const int4*>(&g_q_lo[g]);
    }
    if (tid < 64) { mrow[tid] = -1e30f; lrow[tid] = 0.0f; }

    float o[16];
#pragma unroll
    for (int i = 0; i < 16; i++) o[i] = 0.0f;

    int row = tid >> 2, seg = tid & 3;   // 4 threads per q-row, 16 cols each

    for (int j = 0; j < 32; j++) {
        int k0 = j * 64;
#pragma unroll
        for (int s = 0; s < 2; s++) {
            int v = tid + s * 256;
            int rr = v >> 3, c = (v & 7) * 8;
            size_t g = base + (size_t)(k0 + rr) * 64 + c;
            *reinterpret_cast<int4*>(&Kh[rr * LD + c]) = *reinterpret_cast<const int4*>(&g_k_hi[g]);
            *reinterpret_cast<int4*>(&Kl[rr * LD + c]) = *reinterpret_cast<const int4*>(&g_k_lo[g]);
            *reinterpret_cast<int4*>(&Vh[rr * LD + c]) = *reinterpret_cast<const int4*>(&g_v_hi[g]);
            *reinterpret_cast<int4*>(&Vl[rr * LD + c]) = *reinterpret_cast<const int4*>(&g_v_lo[g]);
        }
        __syncthreads();

        // S = Q K^T  (64x64), split 3-term
#pragma unroll
        for (int i = 0; i < 2; i++) {
            int t = wid * 2 + i, tm = t >> 2, tn = t & 3;
            wmma::fragment<wmma::accumulator, 16, 16, 16, float> sacc;
            wmma::fill_fragment(sacc, 0.0f);
#pragma unroll
            for (int kk = 0; kk < 4; kk++) {
                wmma::fragment<wmma::matrix_a, 16, 16, 16, __half, wmma::row_major> aH, aL;
                wmma::fragment<wmma::matrix_b, 16, 16, 16, __half, wmma::col_major> bH, bL;
                wmma::load_matrix_sync(aH, &Qh[(tm * 16) * LD + kk * 16], LD);
                wmma::load_matrix_sync(aL, &Ql[(tm * 16) * LD + kk * 16], LD);
                wmma::load_matrix_sync(bH, &Kh[(tn * 16) * LD + kk * 16], LD);
                wmma::load_matrix_sync(bL, &Kl[(tn * 16) * LD + kk * 16], LD);
                wmma::mma_sync(sacc, aH, bH, sacc);
                wmma::mma_sync(sacc, aL, bH, sacc);
                wmma::mma_sync(sacc, aH, bL, sacc);
            }
            wmma::store_matrix_sync(&Ss[(tm * 16) * LD + tn * 16], sacc, LD, wmma::mem_row_major);
        }
        __syncthreads();

        // online softmax (fp32)
        {
            float v[16];
            float mloc = -1e30f;
#pragma unroll
            for (int i = 0; i < 16; i++) {
                v[i] = Ss[row * LD + seg * 16 + i];
                mloc = fmaxf(mloc, v[i]);
            }
            mloc = fmaxf(mloc, __shfl_xor_sync(0xffffffffu, mloc, 1));
            mloc = fmaxf(mloc, __shfl_xor_sync(0xffffffffu, mloc, 2));
            float mold = mrow[row];
            float mnew = fmaxf(mold, mloc);
            float corr = __expf(mold - mnew);
            float ssum = 0.0f;
#pragma unroll
            for (int i = 0; i < 16; i++) {
                float p = __expf(v[i] - mnew);
                ssum += p;
                __half ph = __float2half(p);
                Ph[row * LD + seg * 16 + i] = ph;
                Pl[row * LD + seg * 16 + i] = __float2half(p - __half2float(ph));
            }
            ssum += __shfl_xor_sync(0xffffffffu, ssum, 1);
            ssum += __shfl_xor_sync(0xffffffffu, ssum, 2);
            if (seg == 0) { mrow[row] = mnew; lrow[row] = lrow[row] * corr + ssum; }
#pragma unroll
            for (int i = 0; i < 16; i++) o[i] *= corr;
        }
        __syncthreads();

        // PV = P V (64x64), split 3-term, result into Ss
#pragma unroll
        for (int i = 0; i < 2; i++) {
            int t = wid * 2 + i, tm = t >> 2, tn = t & 3;
            wmma::fragment<wmma::accumulator, 16, 16, 16, float> pacc;
            wmma::fill_fragment(pacc, 0.0f);
#pragma unroll
            for (int kk = 0; kk < 4; kk++) {
                wmma::fragment<wmma::matrix_a, 16, 16, 16, __half, wmma::row_major> aH, aL;
                wmma::fragment<wmma::matrix_b, 16, 16, 16, __half, wmma::row_major> bH, bL;
                wmma::load_matrix_sync(aH, &Ph[(tm * 16) * LD + kk * 16], LD);
                wmma::load_matrix_sync(aL, &Pl[(tm * 16) * LD + kk * 16], LD);
                wmma::load_matrix_sync(bH, &Vh[(kk * 16) * LD + tn * 16], LD);
                wmma::load_matrix_sync(bL, &Vl[(kk * 16) * LD + tn * 16], LD);
                wmma::mma_sync(pacc, aH, bH, pacc);
                wmma::mma_sync(pacc, aL, bH, pacc);
                wmma::mma_sync(pacc, aH, bL, pacc);
            }
            wmma::store_matrix_sync(&Ss[(tm * 16) * LD + tn * 16], pacc, LD, wmma::mem_row_major);
        }
        __syncthreads();

#pragma unroll
        for (int i = 0; i < 16; i++) o[i] += Ss[row * LD + seg * 16 + i];
        // no barrier needed here: next iteration's post-load __syncthreads orders
        // these Ss reads against the next S-tile store.
    }

    // epilogue: normalize by row sum, write split halves to (b,l,h*64+hd)
    float linv = 1.0f / lrow[row];
    int b = bh >> 4, h = bh & 15;
    size_t grow = (size_t)(b * 2048 + q0 + row) * 1024 + h * 64 + seg * 16;
#pragma unroll
    for (int i = 0; i < 16; i++) {
        float val = o[i] * linv;
        __half vh = __float2half(val);
        g_aoh[grow + i] = vh;
        g_aol[grow + i] = __float2half(val - __half2float(vh));
    }
}

// ---------------- host launcher ----------------
extern "C" void kernel_launch(void* const* d_in, const int* in_sizes, int n_in,
                              void* d_out, int out_size) {
    (void)in_sizes; (void)n_in; (void)out_size;
    const float* x    = (const float*)d_in[0];
    const float* Wqkv = (const float*)d_in[1];
    const float* bqkv = (const float*)d_in[2];
    const float* qn_w = (const float*)d_in[3];
    const float* kn_w = (const float*)d_in[4];
    const float* Wout = (const float*)d_in[5];
    const float* bout = (const float*)d_in[6];
    float* out = (float*)d_out;

    // split fp32 inputs into (hi,lo) halves
    k_split<<<(MROWS * D_ / 4) / 256, 256>>>(x, 0, MROWS * D_ / 4);
    k_split<<<(D_ * N3D / 4) / 256, 256>>>(Wqkv, 1, D_ * N3D / 4);
    k_split<<<(D_ * D_ / 4) / 256, 256>>>(Wout, 2, D_ * D_ / 4);

    // RoPE table
    k_rope_tab<<<(L_ * 32) / 256, 256>>>();

    // QKV projection: (8192x1024)(1024x3072)
    k_gemm<<<dim3(N3D / 128, MROWS / 128), 256>>>(0, bqkv, nullptr, MROWS, N3D, D_);

    // RMSNorm + RoPE + layout
    k_normrope<<<(MROWS * H_) / 8, 256>>>(qn_w, kn_w);

    // attention
    cudaFuncSetAttribute(k_attn, cudaFuncAttributeMaxDynamicSharedMemorySize, 92672);
    k_attn<<<dim3(L_ / 64, B_ * H_), 256, 92672>>>();

    // output projection: (8192x1024)(1024x1024) + bout -> d_out
    k_gemm<<<dim3(D_ / 128, MROWS / 128), 256>>>(1, bout, out, MROWS, D_, D_);
}

// round 4
// speedup vs baseline: 1.4629x; 1.4629x over previous
#include <cuda_runtime.h>
#include <cuda_fp16.h>
#include <mma.h>

using namespace nvcuda;

// Problem constants
#define B_ 4
#define L_ 2048
#define D_ 1024
#define H_ 16
#define HD_ 64
#define MROWS 8192      // B*L
#define N3D 3072        // 3*D

// ---------------- device scratch (static allocation only) ----------------
__device__ __align__(16) __half g_xh[MROWS * D_];
__device__ __align__(16) __half g_xl[MROWS * D_];
__device__ __align__(16) __half g_wqh[D_ * N3D];
__device__ __align__(16) __half g_wql[D_ * N3D];
__device__ __align__(16) __half g_woh[D_ * D_];
__device__ __align__(16) __half g_wol[D_ * D_];
__device__ __align__(16) float  g_qkv[(size_t)MROWS * N3D];
__device__ __align__(16) __half g_q_hi[64 * 2048 * 64];
__device__ __align__(16) __half g_q_lo[64 * 2048 * 64];
__device__ __align__(16) __half g_k_hi[64 * 2048 * 64];
__device__ __align__(16) __half g_k_lo[64 * 2048 * 64];
__device__ __align__(16) __half g_v_hi[64 * 2048 * 64];
__device__ __align__(16) __half g_v_lo[64 * 2048 * 64];
__device__ __align__(16) __half g_aoh[MROWS * D_];
__device__ __align__(16) __half g_aol[MROWS * D_];
__device__ __align__(16) float  g_cos[L_ * 32];
__device__ __align__(16) float  g_sin[L_ * 32];

// ---------------- PTX helpers ----------------
__device__ __forceinline__ void mma_fp16(float* d, const unsigned* a, unsigned b0, unsigned b1) {
    asm volatile(
        "mma.sync.aligned.m16n8k16.row.col.f32.f16.f16.f32 "
        "{%0,%1,%2,%3}, {%4,%5,%6,%7}, {%8,%9}, {%0,%1,%2,%3};\n"
        : "+f"(d[0]), "+f"(d[1]), "+f"(d[2]), "+f"(d[3])
        : "r"(a[0]), "r"(a[1]), "r"(a[2]), "r"(a[3]), "r"(b0), "r"(b1));
}
__device__ __forceinline__ void ldsm_x4(unsigned& r0, unsigned& r1, unsigned& r2, unsigned& r3, unsigned a) {
    asm volatile("ldmatrix.sync.aligned.m8n8.x4.shared.b16 {%0,%1,%2,%3}, [%4];\n"
                 : "=r"(r0), "=r"(r1), "=r"(r2), "=r"(r3) : "r"(a));
}
__device__ __forceinline__ void ldsm_x4t(unsigned& r0, unsigned& r1, unsigned& r2, unsigned& r3, unsigned a) {
    asm volatile("ldmatrix.sync.aligned.m8n8.x4.trans.shared.b16 {%0,%1,%2,%3}, [%4];\n"
                 : "=r"(r0), "=r"(r1), "=r"(r2), "=r"(r3) : "r"(a));
}
__device__ __forceinline__ void cp_async16(unsigned dst, const void* src) {
    asm volatile("cp.async.cg.shared.global [%0], [%1], 16;\n" :: "r"(dst), "l"(src));
}
__device__ __forceinline__ void cp_commit() { asm volatile("cp.async.commit_group;\n" ::: "memory"); }
template<int N> __device__ __forceinline__ void cp_wait() {
    asm volatile("cp.async.wait_group %0;\n" :: "n"(N) : "memory");
}
__device__ __forceinline__ unsigned pack2(__half a, __half b) {
    __half2 h = __halves2half2(a, b);
    return *reinterpret_cast<unsigned*>(&h);
}

// ---------------- fp32 -> (hi,lo) half split ----------------
__global__ void k_split(const float* __restrict__ src, int which, int n4) {
    __half* hi;
    __half* lo;
    if (which == 0)      { hi = g_xh;  lo = g_xl;  }
    else if (which == 1) { hi = g_wqh; lo = g_wql; }
    else                 { hi = g_woh; lo = g_wol; }
    int i = blockIdx.x * blockDim.x + threadIdx.x;
    if (i >= n4) return;
    float4 v = reinterpret_cast<const float4*>(src)[i];
    __half h0 = __float2half(v.x), h1 = __float2half(v.y);
    __half h2 = __float2half(v.z), h3 = __float2half(v.w);
    __half l0 = __float2half(v.x - __half2float(h0));
    __half l1 = __float2half(v.y - __half2float(h1));
    __half l2 = __float2half(v.z - __half2float(h2));
    __half l3 = __float2half(v.w - __half2float(h3));
    reinterpret_cast<__half2*>(hi)[2 * i]     = __halves2half2(h0, h1);
    reinterpret_cast<__half2*>(hi)[2 * i + 1] = __halves2half2(h2, h3);
    reinterpret_cast<__half2*>(lo)[2 * i]     = __halves2half2(l0, l1);
    reinterpret_cast<__half2*>(lo)[2 * i + 1] = __halves2half2(l2, l3);
}

// ---------------- RoPE cos/sin table (double-precision reduction) ----------------
__global__ void k_rope_tab() {
    int i = blockIdx.x * blockDim.x + threadIdx.x;
    if (i >= L_ * 32) return;
    int l = i >> 5, f = i & 31;
    double invd = pow(10000.0, -(double)(2 * f) / 64.0);
    float invf = (float)invd;
    float ang = (float)l * invf;
    double da = (double)ang;
    g_cos[i] = (float)cos(da);
    g_sin[i] = (float)sin(da);
}

// ---------------- split-fp16 WMMA GEMM, 3-stage cp.async pipeline ----------------
#define GA_LD 40
#define GB_LD 136
#define G_AH 0
#define G_AL (128 * GA_LD)              // 5120 halfs
#define G_BH (2 * 128 * GA_LD)          // 10240
#define G_BL (G_BH + 32 * GB_LD)        // 14592
#define G_STAGE (G_BH + 2 * 32 * GB_LD) // 18944 halfs per stage
#define G_STAG_OFF (3 * G_STAGE * 2)    // 113664 bytes
#define GEMM_SMEM (G_STAG_OFF + 8 * 256 * 4)  // 121856 bytes

__device__ __forceinline__ void gemm_load_stage(unsigned smb, int s,
        const __half* Ah, const __half* Al, const __half* Bh, const __half* Bl,
        int m0, int n0, int k0, int N, int K, int tid) {
#pragma unroll
    for (int t = 0; t < 2; t++) {
        int c = tid + t * 256;
        int ar = c >> 2, ac = (c & 3) * 8;
        unsigned da = smb + (unsigned)((s * G_STAGE + G_AH + ar * GA_LD + ac) * 2);
        cp_async16(da, Ah + (size_t)(m0 + ar) * K + k0 + ac);
        cp_async16(da + (unsigned)((G_AL - G_AH) * 2), Al + (size_t)(m0 + ar) * K + k0 + ac);
        int br = c >> 4, bc = (c & 15) * 8;
        unsigned db = smb + (unsigned)((s * G_STAGE + G_BH + br * GB_LD + bc) * 2);
        cp_async16(db, Bh + (size_t)(k0 + br) * N + n0 + bc);
        cp_async16(db + (unsigned)((G_BL - G_BH) * 2), Bl + (size_t)(k0 + br) * N + n0 + bc);
    }
}

__global__ __launch_bounds__(256, 1) void k_gemm(int which, const float* __restrict__ bias,
                                                 float* __restrict__ Cext,
                                                 int M, int N, int K) {
    extern __shared__ __align__(128) char sm_[];
    __half* smh = (__half*)sm_;
    unsigned smb = (unsigned)__cvta_generic_to_shared(smh);
    float* stag = (float*)(sm_ + G_STAG_OFF);

    const __half* Ah = which ? g_aoh : g_xh;
    const __half* Al = which ? g_aol : g_xl;
    const __half* Bh = which ? g_woh : g_wqh;
    const __half* Bl = which ? g_wol : g_wql;
    float* C = which ? Cext : g_qkv;

    int tid = threadIdx.x;
    int m0 = blockIdx.y * 128, n0 = blockIdx.x * 128;
    int wid = tid >> 5, lane = tid & 31;
    int wm = wid & 3, wn = wid >> 2;   // 4x2 warp grid; warp tile 32x64

    wmma::fragment<wmma::accumulator, 16, 16, 16, float> acc[2][4];
#pragma unroll
    for (int mi = 0; mi < 2; mi++)
#pragma unroll
        for (int ni = 0; ni < 4; ni++) wmma::fill_fragment(acc[mi][ni], 0.0f);

    gemm_load_stage(smb, 0, Ah, Al, Bh, Bl, m0, n0, 0,  N, K, tid); cp_commit();
    gemm_load_stage(smb, 1, Ah, Al, Bh, Bl, m0, n0, 32, N, K, tid); cp_commit();

    int niter = K / 32;
    for (int it = 0; it < niter; it++) {
        if (it < niter - 1) cp_wait<1>(); else cp_wait<0>();
        __syncthreads();
        int s = it - (it / 3) * 3;
        __half* As_h = smh + s * G_STAGE + G_AH;
        __half* As_l = smh + s * G_STAGE + G_AL;
        __half* Bs_h = smh + s * G_STAGE + G_BH;
        __half* Bs_l = smh + s * G_STAGE + G_BL;

#pragma unroll
        for (int kk = 0; kk < 32; kk += 16) {
            wmma::fragment<wmma::matrix_a, 16, 16, 16, __half, wmma::row_major> ah[2], al[2];
#pragma unroll
            for (int mi = 0; mi < 2; mi++) {
                wmma::load_matrix_sync(ah[mi], As_h + (wm * 32 + mi * 16) * GA_LD + kk, GA_LD);
                wmma::load_matrix_sync(al[mi], As_l + (wm * 32 + mi * 16) * GA_LD + kk, GA_LD);
            }
#pragma unroll
            for (int ni = 0; ni < 4; ni++) {
                wmma::fragment<wmma::matrix_b, 16, 16, 16, __half, wmma::row_major> bh, bl;
                wmma::load_matrix_sync(bh, Bs_h + kk * GB_LD + wn * 64 + ni * 16, GB_LD);
                wmma::load_matrix_sync(bl, Bs_l + kk * GB_LD + wn * 64 + ni * 16, GB_LD);
#pragma unroll
                for (int mi = 0; mi < 2; mi++) {
                    wmma::mma_sync(acc[mi][ni], ah[mi], bh, acc[mi][ni]);
                    wmma::mma_sync(acc[mi][ni], al[mi], bh, acc[mi][ni]);
                    wmma::mma_sync(acc[mi][ni], ah[mi], bl, acc[mi][ni]);
                }
            }
        }
        if (it + 2 < niter) {
            int s2 = (it + 2) - ((it + 2) / 3) * 3;
            gemm_load_stage(smb, s2, Ah, Al, Bh, Bl, m0, n0, (it + 2) * 32, N, K, tid);
            cp_commit();
        }
    }

    // epilogue: stage each 16x16 tile through smem, add bias, write fp32
#pragma unroll
    for (int mi = 0; mi < 2; mi++) {
#pragma unroll
        for (int ni = 0; ni < 4; ni++) {
            wmma::store_matrix_sync(&stag[wid * 256], acc[mi][ni], 16, wmma::mem_row_major);
            __syncwarp();
            int r = lane >> 1, c0 = (lane & 1) * 8;
            int gr = m0 + wm * 32 + mi * 16 + r;
            int gc = n0 + wn * 64 + ni * 16 + c0;
#pragma unroll
            for (int j = 0; j < 8; j++)
                C[(size_t)gr * N + gc + j] = stag[wid * 256 + r * 16 + c0 + j] + bias[gc + j];
            __syncwarp();
        }
    }
}

// ---------------- RMSNorm + RoPE + scale, layout to [bh][l][hd], split ----------------
__global__ __launch_bounds__(256) void k_normrope(const float* __restrict__ qn_w,
                                                  const float* __restrict__ kn_w) {
    int gw = blockIdx.x * 8 + (threadIdx.x >> 5);
    int lane = threadIdx.x & 31;
    int r = gw >> 4;
    int h = gw & 15;
    int b = r >> 11;
    int l = r & 2047;
    const float* row = &g_qkv[(size_t)r * N3D];
    float cv = g_cos[l * 32 + lane];
    float sv = g_sin[l * 32 + lane];
    int dst = ((b * 16 + h) * 2048 + l) * 64 + lane;

    {
        float t1 = row[h * 64 + lane];
        float t2 = row[h * 64 + lane + 32];
        float ss = t1 * t1 + t2 * t2;
#pragma unroll
        for (int o = 16; o > 0; o >>= 1) ss += __shfl_xor_sync(0xffffffffu, ss, o);
        float rms = rsqrtf(ss * (1.0f / 64.0f) + 1e-6f);
        t1 *= rms * qn_w[lane];
        t2 *= rms * qn_w[lane + 32];
        float o1 = (t1 * cv - t2 * sv) * 0.125f;
        float o2 = (t1 * sv + t2 * cv) * 0.125f;
        __half a = __float2half(o1);
        g_q_hi[dst] = a; g_q_lo[dst] = __float2half(o1 - __half2float(a));
        __half c = __float2half(o2);
        g_q_hi[dst + 32] = c; g_q_lo[dst + 32] = __float2half(o2 - __half2float(c));
    }
    {
        float t1 = row[1024 + h * 64 + lane];
        float t2 = row[1024 + h * 64 + lane + 32];
        float ss = t1 * t1 + t2 * t2;
#pragma unroll
        for (int o = 16; o > 0; o >>= 1) ss += __shfl_xor_sync(0xffffffffu, ss, o);
        float rms = rsqrtf(ss * (1.0f / 64.0f) + 1e-6f);
        t1 *= rms * kn_w[lane];
        t2 *= rms * kn_w[lane + 32];
        float o1 = t1 * cv - t2 * sv;
        float o2 = t1 * sv + t2 * cv;
        __half a = __float2half(o1);
        g_k_hi[dst] = a; g_k_lo[dst] = __float2half(o1 - __half2float(a));
        __half c = __float2half(o2);
        g_k_hi[dst + 32] = c; g_k_lo[dst + 32] = __float2half(o2 - __half2float(c));
    }
    {
        float v1 = row[2048 + h * 64 + lane];
        float v2 = row[2048 + h * 64 + lane + 32];
        __half a = __float2half(v1);
        g_v_hi[dst] = a; g_v_lo[dst] = __float2half(v1 - __half2float(a));
        __half c = __float2half(v2);
        g_v_hi[dst + 32] = c; g_v_lo[dst + 32] = __float2half(v2 - __half2float(c));
    }
}

// ---------------- FA2-style flash attention, register-resident, 3-stage cp.async ----------------
#define ATT_LD 72
#define ATT_TILE (64 * ATT_LD)        // 4608 halfs per array
#define ATT_STAGE (4 * ATT_TILE)      // 18432 halfs per stage (Kh,Kl,Vh,Vl)
#define ATT_SMEM (3 * ATT_STAGE * 2)  // 110592 bytes

__device__ __forceinline__ void att_load_tile(unsigned smb, size_t gbase, int j, int s, int tid) {
    const __half* src0 = g_k_hi + gbase;
    const __half* src1 = g_k_lo + gbase;
    const __half* src2 = g_v_hi + gbase;
    const __half* src3 = g_v_lo + gbase;
#pragma unroll
    for (int t = 0; t < 2; t++) {
        int c = tid + t * 256;           // 0..511
        int row = c >> 3, col = (c & 7) * 8;
        size_t goff = (size_t)(j * 64 + row) * 64 + col;
        unsigned d = smb + (unsigned)((s * ATT_STAGE + row * ATT_LD + col) * 2);
        cp_async16(d,                              src0 + goff);
        cp_async16(d + (unsigned)(ATT_TILE * 2),     src1 + goff);
        cp_async16(d + (unsigned)(2 * ATT_TILE * 2), src2 + goff);
        cp_async16(d + (unsigned)(3 * ATT_TILE * 2), src3 + goff);
    }
}

__global__ __launch_bounds__(256, 1) void k_attn() {
    extern __shared__ __align__(128) char sm_[];
    unsigned smb = (unsigned)__cvta_generic_to_shared(sm_);

    int tid = threadIdx.x, lane = tid & 31, wid = tid >> 5;
    int bh = blockIdx.y;
    size_t gbase = (size_t)bh * (2048 * 64);
    int q0 = blockIdx.x * 128 + wid * 16;

    // Q fragments (hi/lo) loaded straight from gmem into mma a-frag layout
    unsigned qf[2][4][4];
    {
        const __half* Qh = g_q_hi + gbase;
        const __half* Ql = g_q_lo + gbase;
        int r0 = q0 + (lane >> 2);
        int cb = (lane & 3) * 2;
#pragma unroll
        for (int kk = 0; kk < 4; kk++) {
            int c = kk * 16 + cb;
            qf[0][kk][0] = *(const unsigned*)(Qh + (size_t)r0 * 64 + c);
            qf[0][kk][1] = *(const unsigned*)(Qh + (size_t)(r0 + 8) * 64 + c);
            qf[0][kk][2] = *(const unsigned*)(Qh + (size_t)r0 * 64 + c + 8);
            qf[0][kk][3] = *(const unsigned*)(Qh + (size_t)(r0 + 8) * 64 + c + 8);
            qf[1][kk][0] = *(const unsigned*)(Ql + (size_t)r0 * 64 + c);
            qf[1][kk][1] = *(const unsigned*)(Ql + (size_t)(r0 + 8) * 64 + c);
            qf[1][kk][2] = *(const unsigned*)(Ql + (size_t)r0 * 64 + c + 8);
            qf[1][kk][3] = *(const unsigned*)(Ql + (size_t)(r0 + 8) * 64 + c + 8);
        }
    }

    float oacc[8][4];
#pragma unroll
    for (int t = 0; t < 8; t++) { oacc[t][0] = 0.f; oacc[t][1] = 0.f; oacc[t][2] = 0.f; oacc[t][3] = 0.f; }
    float m0 = -1e30f, m1 = -1e30f, l0 = 0.f, l1 = 0.f;

    att_load_tile(smb, gbase, 0, 0, tid); cp_commit();
    att_load_tile(smb, gbase, 1, 1, tid); cp_commit();

    for (int j = 0; j < 32; j++) {
        int s = j - (j / 3) * 3;
        if (j < 31) cp_wait<1>(); else cp_wait<0>();
        __syncthreads();

        unsigned kbase = smb + (unsigned)(s * ATT_STAGE * 2);          // Kh
        unsigned vbase = kbase + (unsigned)(2 * ATT_TILE * 2);         // Vh

        // ---- S = Q K^T (3-term split), accum in regs ----
        float sacc[8][4];
#pragma unroll
        for (int t = 0; t < 8; t++) { sacc[t][0] = 0.f; sacc[t][1] = 0.f; sacc[t][2] = 0.f; sacc[t][3] = 0.f; }
#pragma unroll
        for (int kk = 0; kk < 4; kk++) {
#pragma unroll
            for (int p = 0; p < 4; p++) {
                int row = p * 16 + ((lane >> 4) << 3) + (lane & 7);
                int col = kk * 16 + ((lane >> 3) & 1) * 8;
                unsigned addr = kbase + (unsigned)((row * ATT_LD + col) * 2);
                unsigned kh0, kh1, kh2, kh3, kl0, kl1, kl2, kl3;
                ldsm_x4(kh0, kh1, kh2, kh3, addr);
                ldsm_x4(kl0, kl1, kl2, kl3, addr + (unsigned)(ATT_TILE * 2));
                mma_fp16(sacc[2 * p],     qf[0][kk], kh0, kh1);
                mma_fp16(sacc[2 * p],     qf[1][kk], kh0, kh1);
                mma_fp16(sacc[2 * p],     qf[0][kk], kl0, kl1);
                mma_fp16(sacc[2 * p + 1], qf[0][kk], kh2, kh3);
                mma_fp16(sacc[2 * p + 1], qf[1][kk], kh2, kh3);
                mma_fp16(sacc[2 * p + 1], qf[0][kk], kl2, kl3);
            }
        }

        // ---- online softmax, all in registers ----
        float mx0 = -1e30f, mx1 = -1e30f;
#pragma unroll
        for (int t = 0; t < 8; t++) {
            mx0 = fmaxf(mx0, fmaxf(sacc[t][0], sacc[t][1]));
            mx1 = fmaxf(mx1, fmaxf(sacc[t][2], sacc[t][3]));
        }
        mx0 = fmaxf(mx0, __shfl_xor_sync(0xffffffffu, mx0, 1));
        mx0 = fmaxf(mx0, __shfl_xor_sync(0xffffffffu, mx0, 2));
        mx1 = fmaxf(mx1, __shfl_xor_sync(0xffffffffu, mx1, 1));
        mx1 = fmaxf(mx1, __shfl_xor_sync(0xffffffffu, mx1, 2));
        float mn0 = fmaxf(m0, mx0), mn1 = fmaxf(m1, mx1);
        float c0 = __expf(m0 - mn0), c1 = __expf(m1 - mn1);
        m0 = mn0; m1 = mn1;

        float ls0 = 0.f, ls1 = 0.f;
        unsigned pf[2][4][4];   // [hi/lo][kstep(kv16)][a-frag regs]
#pragma unroll
        for (int p = 0; p < 4; p++) {
#pragma unroll
            for (int u = 0; u < 2; u++) {
                int t = 2 * p + u;
                float e0 = __expf(sacc[t][0] - mn0);
                float e1 = __expf(sacc[t][1] - mn0);
                float e2 = __expf(sacc[t][2] - mn1);
                float e3 = __expf(sacc[t][3] - mn1);
                ls0 += e0 + e1; ls1 += e2 + e3;
                __half h0 = __float2half_rn(e0), h1 = __float2half_rn(e1);
                __half h2 = __float2half_rn(e2), h3 = __float2half_rn(e3);
                pf[0][p][2 * u]     = pack2(h0, h1);
                pf[0][p][2 * u + 1] = pack2(h2, h3);
                pf[1][p][2 * u]     = pack2(__float2half_rn(e0 - __half2float(h0)),
                                            __float2half_rn(e1 - __half2float(h1)));
                pf[1][p][2 * u + 1] = pack2(__float2half_rn(e2 - __half2float(h2)),
                                            __float2half_rn(e3 - __half2float(h3)));
            }
        }
        ls0 += __shfl_xor_sync(0xffffffffu, ls0, 1);
        ls0 += __shfl_xor_sync(0xffffffffu, ls0, 2);
        ls1 += __shfl_xor_sync(0xffffffffu, ls1, 1);
        ls1 += __shfl_xor_sync(0xffffffffu, ls1, 2);
        l0 = l0 * c0 + ls0;
        l1 = l1 * c1 + ls1;
#pragma unroll
        for (int t = 0; t < 8; t++) { oacc[t][0] *= c0; oacc[t][1] *= c0; oacc[t][2] *= c1; oacc[t][3] *= c1; }

        // ---- O += P V (3-term split) ----
#pragma unroll
        for (int kk = 0; kk < 4; kk++) {
#pragma unroll
            for (int t2 = 0; t2 < 4; t2++) {
                int row = kk * 16 + ((lane >> 3) & 1) * 8 + (lane & 7);
                int col = t2 * 16 + ((lane >> 4) << 3);
                unsigned addr = vbase + (unsigned)((row * ATT_LD + col) * 2);
                unsigned vh0, vh1, vh2, vh3, vl0, vl1, vl2, vl3;
                ldsm_x4t(vh0, vh1, vh2, vh3, addr);
                ldsm_x4t(vl0, vl1, vl2, vl3, addr + (unsigned)(ATT_TILE * 2));
                mma_fp16(oacc[2 * t2],     pf[0][kk], vh0, vh1);
                mma_fp16(oacc[2 * t2],     pf[1][kk], vh0, vh1);
                mma_fp16(oacc[2 * t2],     pf[0][kk], vl0, vl1);
                mma_fp16(oacc[2 * t2 + 1], pf[0][kk], vh2, vh3);
                mma_fp16(oacc[2 * t2 + 1], pf[1][kk], vh2, vh3);
                mma_fp16(oacc[2 * t2 + 1], pf[0][kk], vl2, vl3);
            }
        }

        if (j + 2 < 32) {
            int s2 = (j + 2) - ((j + 2) / 3) * 3;
            att_load_tile(smb, gbase, j + 2, s2, tid);
            cp_commit();
        }
    }

    // ---- epilogue: normalize, split, store to [b,l,h*64+hd] ----
    float i0 = 1.0f / l0, i1 = 1.0f / l1;
    int b = bh >> 4, h = bh & 15;
    int r = q0 + (lane >> 2);
    size_t ob0 = (size_t)(b * 2048 + r) * 1024 + h * 64;
    size_t ob1 = ob0 + (size_t)8 * 1024;
#pragma unroll
    for (int t = 0; t < 8; t++) {
        int c = t * 8 + (lane & 3) * 2;
        float v0 = oacc[t][0] * i0, v1 = oacc[t][1] * i0;
        float v2 = oacc[t][2] * i1, v3 = oacc[t][3] * i1;
        __half h0 = __float2half_rn(v0), h1 = __float2half_rn(v1);
        __half h2 = __float2half_rn(v2), h3 = __float2half_rn(v3);
        *(unsigned*)(g_aoh + ob0 + c) = pack2(h0, h1);
        *(unsigned*)(g_aoh + ob1 + c) = pack2(h2, h3);
        *(unsigned*)(g_aol + ob0 + c) = pack2(__float2half_rn(v0 - __half2float(h0)),
                                              __float2half_rn(v1 - __half2float(h1)));
        *(unsigned*)(g_aol + ob1 + c) = pack2(__float2half_rn(v2 - __half2float(h2)),
                                              __float2half_rn(v3 - __half2float(h3)));
    }
}

// ---------------- host launcher ----------------
extern "C" void kernel_launch(void* const* d_in, const int* in_sizes, int n_in,
                              void* d_out, int out_size) {
    (void)in_sizes; (void)n_in; (void)out_size;
    const float* x    = (const float*)d_in[0];
    const float* Wqkv = (const float*)d_in[1];
    const float* bqkv = (const float*)d_in[2];
    const float* qn_w = (const float*)d_in[3];
    const float* kn_w = (const float*)d_in[4];
    const float* Wout = (const float*)d_in[5];
    const float* bout = (const float*)d_in[6];
    float* out = (float*)d_out;

    // split fp32 inputs into (hi,lo) halves
    k_split<<<(MROWS * D_ / 4) / 256, 256>>>(x, 0, MROWS * D_ / 4);
    k_split<<<(D_ * N3D / 4) / 256, 256>>>(Wqkv, 1, D_ * N3D / 4);
    k_split<<<(D_ * D_ / 4) / 256, 256>>>(Wout, 2, D_ * D_ / 4);

    // RoPE table
    k_rope_tab<<<(L_ * 32) / 256, 256>>>();

    // QKV projection: (8192x1024)(1024x3072)
    cudaFuncSetAttribute(k_gemm, cudaFuncAttributeMaxDynamicSharedMemorySize, GEMM_SMEM);
    k_gemm<<<dim3(N3D / 128, MROWS / 128), 256, GEMM_SMEM>>>(0, bqkv, nullptr, MROWS, N3D, D_);

    // RMSNorm + RoPE + layout
    k_normrope<<<(MROWS * H_) / 8, 256>>>(qn_w, kn_w);

    // attention (BM=128, BN=64, register-resident FA2)
    cudaFuncSetAttribute(k_attn, cudaFuncAttributeMaxDynamicSharedMemorySize, ATT_SMEM);
    k_attn<<<dim3(L_ / 128, B_ * H_), 256, ATT_SMEM>>>();

    // output projection: (8192x1024)(1024x1024) + bout -> d_out
    k_gemm<<<dim3(D_ / 128, MROWS / 128), 256, GEMM_SMEM>>>(1, bout, out, MROWS, D_, D_);
}

// round 6
// speedup vs baseline: 1.5279x; 1.0445x over previous
#include <cuda_runtime.h>
#include <cuda_fp16.h>
#include <mma.h>

using namespace nvcuda;

// Problem constants
#define B_ 4
#define L_ 2048
#define D_ 1024
#define H_ 16
#define HD_ 64
#define MROWS 8192      // B*L
#define N3D 3072        // 3*D

// ---------------- device scratch (static allocation only) ----------------
__device__ __align__(16) __half g_xh[MROWS * D_];
__device__ __align__(16) __half g_xl[MROWS * D_];
__device__ __align__(16) __half g_wqh[D_ * N3D];   // [K][N] layout
__device__ __align__(16) __half g_wql[D_ * N3D];
__device__ __align__(16) __half g_woh[D_ * D_];
__device__ __align__(16) __half g_wol[D_ * D_];
__device__ __align__(16) __half g_q_hi[64 * 2048 * 64];
__device__ __align__(16) __half g_q_lo[64 * 2048 * 64];
__device__ __align__(16) __half g_k_hi[64 * 2048 * 64];
__device__ __align__(16) __half g_k_lo[64 * 2048 * 64];
__device__ __align__(16) __half g_v_hi[64 * 2048 * 64];
__device__ __align__(16) __half g_v_lo[64 * 2048 * 64];
__device__ __align__(16) __half g_aoh[MROWS * D_];
__device__ __align__(16) __half g_aol[MROWS * D_];
__device__ __align__(16) float  g_cos[L_ * 32];
__device__ __align__(16) float  g_sin[L_ * 32];

// ---------------- PTX helpers ----------------
__device__ __forceinline__ void mma_fp16(float* d, const unsigned* a, unsigned b0, unsigned b1) {
    asm volatile(
        "mma.sync.aligned.m16n8k16.row.col.f32.f16.f16.f32 "
        "{%0,%1,%2,%3}, {%4,%5,%6,%7}, {%8,%9}, {%0,%1,%2,%3};\n"
        : "+f"(d[0]), "+f"(d[1]), "+f"(d[2]), "+f"(d[3])
        : "r"(a[0]), "r"(a[1]), "r"(a[2]), "r"(a[3]), "r"(b0), "r"(b1));
}
__device__ __forceinline__ void ldsm_x4(unsigned& r0, unsigned& r1, unsigned& r2, unsigned& r3, unsigned a) {
    asm volatile("ldmatrix.sync.aligned.m8n8.x4.shared.b16 {%0,%1,%2,%3}, [%4];\n"
                 : "=r"(r0), "=r"(r1), "=r"(r2), "=r"(r3) : "r"(a));
}
__device__ __forceinline__ void ldsm_x4t(unsigned& r0, unsigned& r1, unsigned& r2, unsigned& r3, unsigned a) {
    asm volatile("ldmatrix.sync.aligned.m8n8.x4.trans.shared.b16 {%0,%1,%2,%3}, [%4];\n"
                 : "=r"(r0), "=r"(r1), "=r"(r2), "=r"(r3) : "r"(a));
}
__device__ __forceinline__ void cp_async16(unsigned dst, const void* src) {
    asm volatile("cp.async.cg.shared.global [%0], [%1], 16;\n" :: "r"(dst), "l"(src));
}
__device__ __forceinline__ void cp_commit() { asm volatile("cp.async.commit_group;\n" ::: "memory"); }
template<int N> __device__ __forceinline__ void cp_wait() {
    asm volatile("cp.async.wait_group %0;\n" :: "n"(N) : "memory");
}
__device__ __forceinline__ unsigned pack2(__half a, __half b) {
    __half2 h = __halves2half2(a, b);
    return *reinterpret_cast<unsigned*>(&h);
}

// ---------------- x split (fp32 -> hi/lo halves) + fused RoPE table ----------------
__global__ void k_split_x(const float* __restrict__ src, int n4) {
    int i = blockIdx.x * blockDim.x + threadIdx.x;
    if (blockIdx.x < 256) {
        int idx = blockIdx.x * 256 + threadIdx.x;   // < 65536 = L_*32
        int l = idx >> 5, f = idx & 31;
        double invd = pow(10000.0, -(double)(2 * f) / 64.0);
        float invf = (float)invd;        // fp32 inv_freq matches jax value
        float ang = (float)l * invf;     // fp32 angle matches reference rounding
        double da = (double)ang;
        g_cos[idx] = (float)cos(da);
        g_sin[idx] = (float)sin(da);
    }
    if (i >= n4) return;
    float4 v = reinterpret_cast<const float4*>(src)[i];
    __half h0 = __float2half(v.x), h1 = __float2half(v.y);
    __half h2 = __float2half(v.z), h3 = __float2half(v.w);
    __half l0 = __float2half(v.x - __half2float(h0));
    __half l1 = __float2half(v.y - __half2float(h1));
    __half l2 = __float2half(v.z - __half2float(h2));
    __half l3 = __float2half(v.w - __half2float(h3));
    reinterpret_cast<__half2*>(g_xh)[2 * i]     = __halves2half2(h0, h1);
    reinterpret_cast<__half2*>(g_xh)[2 * i + 1] = __halves2half2(h2, h3);
    reinterpret_cast<__half2*>(g_xl)[2 * i]     = __halves2half2(l0, l1);
    reinterpret_cast<__half2*>(g_xl)[2 * i + 1] = __halves2half2(l2, l3);
}

// ---------------- weight split (keeps [K][N] layout) ----------------
__global__ void k_split_w(const float* __restrict__ src, int which, int n4) {
    __half* hi = (which == 1) ? g_wqh : g_woh;
    __half* lo = (which == 1) ? g_wql : g_wol;
    int i = blockIdx.x * blockDim.x + threadIdx.x;
    if (i >= n4) return;
    float4 v = reinterpret_cast<const float4*>(src)[i];
    __half h0 = __float2half(v.x), h1 = __float2half(v.y);
    __half h2 = __float2half(v.z), h3 = __float2half(v.w);
    __half l0 = __float2half(v.x - __half2float(h0));
    __half l1 = __float2half(v.y - __half2float(h1));
    __half l2 = __float2half(v.z - __half2float(h2));
    __half l3 = __float2half(v.w - __half2float(h3));
    reinterpret_cast<__half2*>(hi)[2 * i]     = __halves2half2(h0, h1);
    reinterpret_cast<__half2*>(hi)[2 * i + 1] = __halves2half2(h2, h3);
    reinterpret_cast<__half2*>(lo)[2 * i]     = __halves2half2(l0, l1);
    reinterpret_cast<__half2*>(lo)[2 * i + 1] = __halves2half2(l2, l3);
}

// ---------------- split-fp16 WMMA GEMM, 3-stage cp.async pipeline ----------------
// which==0: A=x(split), B=Wqkv(split), fused epilogue: bias+rmsnorm+rope+split -> g_{q,k,v}_{hi,lo}
// which==1: A=attn_out(split), B=Wout(split), epilogue: bias -> Cext fp32
#define GA_LD 40
#define GB_LD 136
#define G_AH 0
#define G_AL (128 * GA_LD)              // 5120 halfs
#define G_BH (2 * 128 * GA_LD)          // 10240
#define G_BL (G_BH + 32 * GB_LD)        // 14592
#define G_STAGE (G_BH + 2 * 32 * GB_LD) // 18944 halfs per stage
#define GEMM_SMEM (3 * G_STAGE * 2)     // 113664 bytes (staging reuses this)

__device__ __forceinline__ void gemm_load_stage(unsigned smb, int s,
        const __half* Ah, const __half* Al, const __half* Bh, const __half* Bl,
        int m0, int n0, int k0, int N, int K, int tid) {
#pragma unroll
    for (int t = 0; t < 2; t++) {
        int c = tid + t * 256;
        int ar = c >> 2, ac = (c & 3) * 8;
        unsigned da = smb + (unsigned)((s * G_STAGE + G_AH + ar * GA_LD + ac) * 2);
        cp_async16(da, Ah + (size_t)(m0 + ar) * K + k0 + ac);
        cp_async16(da + (unsigned)((G_AL - G_AH) * 2), Al + (size_t)(m0 + ar) * K + k0 + ac);
        int br = c >> 4, bc = (c & 15) * 8;
        unsigned db = smb + (unsigned)((s * G_STAGE + G_BH + br * GB_LD + bc) * 2);
        cp_async16(db, Bh + (size_t)(k0 + br) * N + n0 + bc);
        cp_async16(db + (unsigned)((G_BL - G_BH) * 2), Bl + (size_t)(k0 + br) * N + n0 + bc);
    }
}

__global__ __launch_bounds__(256, 1) void k_gemm(int which, const float* __restrict__ bias,
                                                 const float* __restrict__ qn_w,
                                                 const float* __restrict__ kn_w,
                                                 float* __restrict__ Cext,
                                                 int M, int N, int K) {
    extern __shared__ __align__(128) char sm_[];
    __half* smh = (__half*)sm_;
    unsigned smb = (unsigned)__cvta_generic_to_shared(smh);

    const __half* Ah = which ? g_aoh : g_xh;
    const __half* Al = which ? g_aol : g_xl;
    const __half* Bh = which ? g_woh : g_wqh;
    const __half* Bl = which ? g_wol : g_wql;

    int tid = threadIdx.x;
    int m0 = blockIdx.y * 128, n0 = blockIdx.x * 128;
    int wid = tid >> 5, lane = tid & 31;
    int wm = wid & 3, wn = wid >> 2;   // 4x2 warp grid; warp tile 32 rows x 64 cols

    wmma::fragment<wmma::accumulator, 16, 16, 16, float> acc[2][4];
#pragma unroll
    for (int mi = 0; mi < 2; mi++)
#pragma unroll
        for (int ni = 0; ni < 4; ni++) wmma::fill_fragment(acc[mi][ni], 0.0f);

    gemm_load_stage(smb, 0, Ah, Al, Bh, Bl, m0, n0, 0,  N, K, tid); cp_commit();
    gemm_load_stage(smb, 1, Ah, Al, Bh, Bl, m0, n0, 32, N, K, tid); cp_commit();

    int niter = K / 32;
    for (int it = 0; it < niter; it++) {
        if (it < niter - 1) cp_wait<1>(); else cp_wait<0>();
        __syncthreads();
        int s = it - (it / 3) * 3;
        __half* As_h = smh + s * G_STAGE + G_AH;
        __half* As_l = smh + s * G_STAGE + G_AL;
        __half* Bs_h = smh + s * G_STAGE + G_BH;
        __half* Bs_l = smh + s * G_STAGE + G_BL;

#pragma unroll
        for (int kk = 0; kk < 32; kk += 16) {
            wmma::fragment<wmma::matrix_a, 16, 16, 16, __half, wmma::row_major> ah[2], al[2];
#pragma unroll
            for (int mi = 0; mi < 2; mi++) {
                wmma::load_matrix_sync(ah[mi], As_h + (wm * 32 + mi * 16) * GA_LD + kk, GA_LD);
                wmma::load_matrix_sync(al[mi], As_l + (wm * 32 + mi * 16) * GA_LD + kk, GA_LD);
            }
#pragma unroll
            for (int ni = 0; ni < 4; ni++) {
                wmma::fragment<wmma::matrix_b, 16, 16, 16, __half, wmma::row_major> bh, bl;
                wmma::load_matrix_sync(bh, Bs_h + kk * GB_LD + wn * 64 + ni * 16, GB_LD);
                wmma::load_matrix_sync(bl, Bs_l + kk * GB_LD + wn * 64 + ni * 16, GB_LD);
#pragma unroll
                for (int mi = 0; mi < 2; mi++) {
                    wmma::mma_sync(acc[mi][ni], ah[mi], bh, acc[mi][ni]);
                    wmma::mma_sync(acc[mi][ni], al[mi], bh, acc[mi][ni]);
                    wmma::mma_sync(acc[mi][ni], ah[mi], bl, acc[mi][ni]);
                }
            }
        }
        if (it + 2 < niter) {
            int s2 = (it + 2) - ((it + 2) / 3) * 3;
            gemm_load_stage(smb, s2, Ah, Al, Bh, Bl, m0, n0, (it + 2) * 32, N, K, tid);
            cp_commit();
        }
    }

    // ---- epilogue: stage warp tile (32x64) to smem, one lane per row ----
    __syncthreads();                       // pipeline smem free for staging
    float* st = (float*)sm_ + (size_t)wid * (32 * 68);
#pragma unroll
    for (int mi = 0; mi < 2; mi++)
#pragma unroll
        for (int ni = 0; ni < 4; ni++)
            wmma::store_matrix_sync(st + (mi * 16) * 68 + ni * 16, acc[mi][ni], 68,
                                    wmma::mem_row_major);
    __syncwarp();

    int gr = m0 + wm * 32 + lane;          // global row
    int gn0 = n0 + wn * 64;                // global col base (64-aligned => single head/matrix)
    float* rp = st + lane * 68;

    if (which == 0) {
        int sel = gn0 >> 10;               // 0=Q, 1=K, 2=V
        int h = (gn0 & 1023) >> 6;
        int b = gr >> 11, l = gr & 2047;
        size_t dst = ((size_t)(b * 16 + h) * 2048 + l) * 64;
        __half *hi, *lo;
        if (sel == 0)      { hi = g_q_hi; lo = g_q_lo; }
        else if (sel == 1) { hi = g_k_hi; lo = g_k_lo; }
        else               { hi = g_v_hi; lo = g_v_lo; }

        if (sel == 2) {
#pragma unroll
            for (int c = 0; c < 64; c += 2) {
                float v0 = rp[c]     + bias[gn0 + c];
                float v1 = rp[c + 1] + bias[gn0 + c + 1];
                __half a0 = __float2half(v0), a1 = __float2half(v1);
                *(unsigned*)(hi + dst + c) = pack2(a0, a1);
                *(unsigned*)(lo + dst + c) = pack2(__float2half(v0 - __half2float(a0)),
                                                   __float2half(v1 - __half2float(a1)));
            }
        } else {
            const float* w = (sel == 0) ? qn_w : kn_w;
            float ss = 0.f;
#pragma unroll
            for (int c = 0; c < 64; c++) {
                float v = rp[c] + bias[gn0 + c];
                rp[c] = v;
                ss += v * v;
            }
            float rms = rsqrtf(ss * (1.0f / 64.0f) + 1e-6f);
            float qs = (sel == 0) ? 0.125f : 1.0f;   // fold attn scale into Q
#pragma unroll
            for (int c = 0; c < 32; c += 2) {
                float cv0 = g_cos[l * 32 + c],     sv0 = g_sin[l * 32 + c];
                float cv1 = g_cos[l * 32 + c + 1], sv1 = g_sin[l * 32 + c + 1];
                float t10 = rp[c]      * rms * w[c];
                float t11 = rp[c + 1]  * rms * w[c + 1];
                float t20 = rp[c + 32] * rms * w[c + 32];
                float t21 = rp[c + 33] * rms * w[c + 33];
                float o10 = (t10 * cv0 - t20 * sv0) * qs;
                float o11 = (t11 * cv1 - t21 * sv1) * qs;
                float o20 = (t10 * sv0 + t20 * cv0) * qs;
                float o21 = (t11 * sv1 + t21 * cv1) * qs;
                __half a0 = __float2half(o10), a1 = __float2half(o11);
                __half b0 = __float2half(o20), b1 = __float2half(o21);
                *(unsigned*)(hi + dst + c)      = pack2(a0, a1);
                *(unsigned*)(hi + dst + 32 + c) = pack2(b0, b1);
                *(unsigned*)(lo + dst + c)      = pack2(__float2half(o10 - __half2float(a0)),
                                                        __float2half(o11 - __half2float(a1)));
                *(unsigned*)(lo + dst + 32 + c) = pack2(__float2half(o20 - __half2float(b0)),
                                                        __float2half(o21 - __half2float(b1)));
            }
        }
    } else {
        float* dst = Cext + (size_t)gr * N + gn0;
#pragma unroll
        for (int c = 0; c < 64; c += 4) {
            float4 v;
            v.x = rp[c]     + bias[gn0 + c];
            v.y = rp[c + 1] + bias[gn0 + c + 1];
            v.z = rp[c + 2] + bias[gn0 + c + 2];
            v.w = rp[c + 3] + bias[gn0 + c + 3];
            *reinterpret_cast<float4*>(dst + c) = v;
        }
    }
}

// ---------------- FA2-style flash attention, register-resident, 3-stage cp.async ----------------
#define ATT_LD 72
#define ATT_TILE (64 * ATT_LD)
#define ATT_STAGE (4 * ATT_TILE)
#define ATT_SMEM (3 * ATT_STAGE * 2)

__device__ __forceinline__ void att_load_tile(unsigned smb, size_t gbase, int j, int s, int tid) {
    const __half* src0 = g_k_hi + gbase;
    const __half* src1 = g_k_lo + gbase;
    const __half* src2 = g_v_hi + gbase;
    const __half* src3 = g_v_lo + gbase;
#pragma unroll
    for (int t = 0; t < 2; t++) {
        int c = tid + t * 256;
        int row = c >> 3, col = (c & 7) * 8;
        size_t goff = (size_t)(j * 64 + row) * 64 + col;
        unsigned d = smb + (unsigned)((s * ATT_STAGE + row * ATT_LD + col) * 2);
        cp_async16(d,                                src0 + goff);
        cp_async16(d + (unsigned)(ATT_TILE * 2),     src1 + goff);
        cp_async16(d + (unsigned)(2 * ATT_TILE * 2), src2 + goff);
        cp_async16(d + (unsigned)(3 * ATT_TILE * 2), src3 + goff);
    }
}

__global__ __launch_bounds__(256, 1) void k_attn() {
    extern __shared__ __align__(128) char sm_[];
    unsigned smb = (unsigned)__cvta_generic_to_shared(sm_);

    int tid = threadIdx.x, lane = tid & 31, wid = tid >> 5;
    int bh = blockIdx.y;
    size_t gbase = (size_t)bh * (2048 * 64);
    int q0 = blockIdx.x * 128 + wid * 16;

    unsigned qf[2][4][4];
    {
        const __half* Qh = g_q_hi + gbase;
        const __half* Ql = g_q_lo + gbase;
        int r0 = q0 + (lane >> 2);
        int cb = (lane & 3) * 2;
#pragma unroll
        for (int kk = 0; kk < 4; kk++) {
            int c = kk * 16 + cb;
            qf[0][kk][0] = *(const unsigned*)(Qh + (size_t)r0 * 64 + c);
            qf[0][kk][1] = *(const unsigned*)(Qh + (size_t)(r0 + 8) * 64 + c);
            qf[0][kk][2] = *(const unsigned*)(Qh + (size_t)r0 * 64 + c + 8);
            qf[0][kk][3] = *(const unsigned*)(Qh + (size_t)(r0 + 8) * 64 + c + 8);
            qf[1][kk][0] = *(const unsigned*)(Ql + (size_t)r0 * 64 + c);
            qf[1][kk][1] = *(const unsigned*)(Ql + (size_t)(r0 + 8) * 64 + c);
            qf[1][kk][2] = *(const unsigned*)(Ql + (size_t)r0 * 64 + c + 8);
            qf[1][kk][3] = *(const unsigned*)(Ql + (size_t)(r0 + 8) * 64 + c + 8);
        }
    }

    float oacc[8][4];
#pragma unroll
    for (int t = 0; t < 8; t++) { oacc[t][0] = 0.f; oacc[t][1] = 0.f; oacc[t][2] = 0.f; oacc[t][3] = 0.f; }
    float m0 = -1e30f, m1 = -1e30f, l0 = 0.f, l1 = 0.f;

    att_load_tile(smb, gbase, 0, 0, tid); cp_commit();
    att_load_tile(smb, gbase, 1, 1, tid); cp_commit();

    for (int j = 0; j < 32; j++) {
        int s = j - (j / 3) * 3;
        if (j < 31) cp_wait<1>(); else cp_wait<0>();
        __syncthreads();

        unsigned kbase = smb + (unsigned)(s * ATT_STAGE * 2);
        unsigned vbase = kbase + (unsigned)(2 * ATT_TILE * 2);

        float sacc[8][4];
#pragma unroll
        for (int t = 0; t < 8; t++) { sacc[t][0] = 0.f; sacc[t][1] = 0.f; sacc[t][2] = 0.f; sacc[t][3] = 0.f; }
#pragma unroll
        for (int kk = 0; kk < 4; kk++) {
#pragma unroll
            for (int p = 0; p < 4; p++) {
                int row = p * 16 + ((lane >> 4) << 3) + (lane & 7);
                int col = kk * 16 + ((lane >> 3) & 1) * 8;
                unsigned addr = kbase + (unsigned)((row * ATT_LD + col) * 2);
                unsigned kh0, kh1, kh2, kh3, kl0, kl1, kl2, kl3;
                ldsm_x4(kh0, kh1, kh2, kh3, addr);
                ldsm_x4(kl0, kl1, kl2, kl3, addr + (unsigned)(ATT_TILE * 2));
                mma_fp16(sacc[2 * p],     qf[0][kk], kh0, kh1);
                mma_fp16(sacc[2 * p],     qf[1][kk], kh0, kh1);
                mma_fp16(sacc[2 * p],     qf[0][kk], kl0, kl1);
                mma_fp16(sacc[2 * p + 1], qf[0][kk], kh2, kh3);
                mma_fp16(sacc[2 * p + 1], qf[1][kk], kh2, kh3);
                mma_fp16(sacc[2 * p + 1], qf[0][kk], kl2, kl3);
            }
        }

        float mx0 = -1e30f, mx1 = -1e30f;
#pragma unroll
        for (int t = 0; t < 8; t++) {
            mx0 = fmaxf(mx0, fmaxf(sacc[t][0], sacc[t][1]));
            mx1 = fmaxf(mx1, fmaxf(sacc[t][2], sacc[t][3]));
        }
        mx0 = fmaxf(mx0, __shfl_xor_sync(0xffffffffu, mx0, 1));
        mx0 = fmaxf(mx0, __shfl_xor_sync(0xffffffffu, mx0, 2));
        mx1 = fmaxf(mx1, __shfl_xor_sync(0xffffffffu, mx1, 1));
        mx1 = fmaxf(mx1, __shfl_xor_sync(0xffffffffu, mx1, 2));
        float mn0 = fmaxf(m0, mx0), mn1 = fmaxf(m1, mx1);
        float c0 = __expf(m0 - mn0), c1 = __expf(m1 - mn1);
        m0 = mn0; m1 = mn1;

        float ls0 = 0.f, ls1 = 0.f;
        unsigned pf[2][4][4];
#pragma unroll
        for (int p = 0; p < 4; p++) {
#pragma unroll
            for (int u = 0; u < 2; u++) {
                int t = 2 * p + u;
                float e0 = __expf(sacc[t][0] - mn0);
                float e1 = __expf(sacc[t][1] - mn0);
                float e2 = __expf(sacc[t][2] - mn1);
                float e3 = __expf(sacc[t][3] - mn1);
                ls0 += e0 + e1; ls1 += e2 + e3;
                __half h0 = __float2half_rn(e0), h1 = __float2half_rn(e1);
                __half h2 = __float2half_rn(e2), h3 = __float2half_rn(e3);
                pf[0][p][2 * u]     = pack2(h0, h1);
                pf[0][p][2 * u + 1] = pack2(h2, h3);
                pf[1][p][2 * u]     = pack2(__float2half_rn(e0 - __half2float(h0)),
                                            __float2half_rn(e1 - __half2float(h1)));
                pf[1][p][2 * u + 1] = pack2(__float2half_rn(e2 - __half2float(h2)),
                                            __float2half_rn(e3 - __half2float(h3)));
            }
        }
        ls0 += __shfl_xor_sync(0xffffffffu, ls0, 1);
        ls0 += __shfl_xor_sync(0xffffffffu, ls0, 2);
        ls1 += __shfl_xor_sync(0xffffffffu, ls1, 1);
        ls1 += __shfl_xor_sync(0xffffffffu, ls1, 2);
        l0 = l0 * c0 + ls0;
        l1 = l1 * c1 + ls1;
#pragma unroll
        for (int t = 0; t < 8; t++) { oacc[t][0] *= c0; oacc[t][1] *= c0; oacc[t][2] *= c1; oacc[t][3] *= c1; }

#pragma unroll
        for (int kk = 0; kk < 4; kk++) {
#pragma unroll
            for (int t2 = 0; t2 < 4; t2++) {
                int row = kk * 16 + ((lane >> 3) & 1) * 8 + (lane & 7);
                int col = t2 * 16 + ((lane >> 4) << 3);
                unsigned addr = vbase + (unsigned)((row * ATT_LD + col) * 2);
                unsigned vh0, vh1, vh2, vh3, vl0, vl1, vl2, vl3;
                ldsm_x4t(vh0, vh1, vh2, vh3, addr);
                ldsm_x4t(vl0, vl1, vl2, vl3, addr + (unsigned)(ATT_TILE * 2));
                mma_fp16(oacc[2 * t2],     pf[0][kk], vh0, vh1);
                mma_fp16(oacc[2 * t2],     pf[1][kk], vh0, vh1);
                mma_fp16(oacc[2 * t2],     pf[0][kk], vl0, vl1);
                mma_fp16(oacc[2 * t2 + 1], pf[0][kk], vh2, vh3);
                mma_fp16(oacc[2 * t2 + 1], pf[1][kk], vh2, vh3);
                mma_fp16(oacc[2 * t2 + 1], pf[0][kk], vl2, vl3);
            }
        }

        if (j + 2 < 32) {
            int s2 = (j + 2) - ((j + 2) / 3) * 3;
            att_load_tile(smb, gbase, j + 2, s2, tid);
            cp_commit();
        }
    }

    float i0 = 1.0f / l0, i1 = 1.0f / l1;
    int b = bh >> 4, h = bh & 15;
    int r = q0 + (lane >> 2);
    size_t ob0 = (size_t)(b * 2048 + r) * 1024 + h * 64;
    size_t ob1 = ob0 + (size_t)8 * 1024;
#pragma unroll
    for (int t = 0; t < 8; t++) {
        int c = t * 8 + (lane & 3) * 2;
        float v0 = oacc[t][0] * i0, v1 = oacc[t][1] * i0;
        float v2 = oacc[t][2] * i1, v3 = oacc[t][3] * i1;
        __half h0 = __float2half_rn(v0), h1 = __float2half_rn(v1);
        __half h2 = __float2half_rn(v2), h3 = __float2half_rn(v3);
        *(unsigned*)(g_aoh + ob0 + c) = pack2(h0, h1);
        *(unsigned*)(g_aoh + ob1 + c) = pack2(h2, h3);
        *(unsigned*)(g_aol + ob0 + c) = pack2(__float2half_rn(v0 - __half2float(h0)),
                                              __float2half_rn(v1 - __half2float(h1)));
        *(unsigned*)(g_aol + ob1 + c) = pack2(__float2half_rn(v2 - __half2float(h2)),
                                              __float2half_rn(v3 - __half2float(h3)));
    }
}

// ---------------- host launcher ----------------
extern "C" void kernel_launch(void* const* d_in, const int* in_sizes, int n_in,
                              void* d_out, int out_size) {
    (void)in_sizes; (void)n_in; (void)out_size;
    const float* x    = (const float*)d_in[0];
    const float* Wqkv = (const float*)d_in[1];
    const float* bqkv = (const float*)d_in[2];
    const float* qn_w = (const float*)d_in[3];
    const float* kn_w = (const float*)d_in[4];
    const float* Wout = (const float*)d_in[5];
    const float* bout = (const float*)d_in[6];
    float* out = (float*)d_out;

    // [0] split x + fused RoPE table
    k_split_x<<<(MROWS * D_ / 4) / 256, 256>>>(x, MROWS * D_ / 4);
    // [1][2] split weights
    k_split_w<<<(D_ * N3D / 4) / 256, 256>>>(Wqkv, 1, D_ * N3D / 4);
    k_split_w<<<(D_ * D_ / 4) / 256, 256>>>(Wout, 2, D_ * D_ / 4);

    // [3] QKV projection + fused bias/rmsnorm/rope/split epilogue (ncu-captured launch)
    cudaFuncSetAttribute(k_gemm, cudaFuncAttributeMaxDynamicSharedMemorySize, GEMM_SMEM);
    k_gemm<<<dim3(N3D / 128, MROWS / 128), 256, GEMM_SMEM>>>(0, bqkv, qn_w, kn_w, nullptr,
                                                             MROWS, N3D, D_);

    // [4] attention (BM=128, BN=64, register-resident FA2)
    cudaFuncSetAttribute(k_attn, cudaFuncAttributeMaxDynamicSharedMemorySize, ATT_SMEM);
    k_attn<<<dim3(L_ / 128, B_ * H_), 256, ATT_SMEM>>>();

    // [5] output projection + bias -> d_out
    k_gemm<<<dim3(D_ / 128, MROWS / 128), 256, GEMM_SMEM>>>(1, bout, qn_w, kn_w, out,
                                                            MROWS, D_, D_);
}

// round 8
// speedup vs baseline: 1.6349x; 1.0700x over previous
#include <cuda_runtime.h>
#include <cuda_fp16.h>

// Problem constants
#define B_ 4
#define L_ 2048
#define D_ 1024
#define H_ 16
#define HD_ 64
#define MROWS 8192      // B*L
#define N3D 3072        // 3*D

// ---------------- device scratch (static allocation only) ----------------
__device__ __align__(16) __half g_xh[MROWS * D_];
__device__ __align__(16) __half g_xl[MROWS * D_];
__device__ __align__(16) __half g_wqh[D_ * N3D];   // [K][N] layout
__device__ __align__(16) __half g_wql[D_ * N3D];
__device__ __align__(16) __half g_woh[D_ * D_];
__device__ __align__(16) __half g_wol[D_ * D_];
__device__ __align__(16) __half g_q_hi[64 * 2048 * 64];
__device__ __align__(16) __half g_q_lo[64 * 2048 * 64];
__device__ __align__(16) __half g_k_hi[64 * 2048 * 64];
__device__ __align__(16) __half g_k_lo[64 * 2048 * 64];
__device__ __align__(16) __half g_v_hi[64 * 2048 * 64];
__device__ __align__(16) __half g_v_lo[64 * 2048 * 64];
__device__ __align__(16) __half g_aoh[MROWS * D_];
__device__ __align__(16) __half g_aol[MROWS * D_];
__device__ __align__(16) float  g_cos[L_ * 32];
__device__ __align__(16) float  g_sin[L_ * 32];

// ---------------- PTX helpers ----------------
__device__ __forceinline__ void mma_fp16(float* d, const unsigned* a, unsigned b0, unsigned b1) {
    asm volatile(
        "mma.sync.aligned.m16n8k16.row.col.f32.f16.f16.f32 "
        "{%0,%1,%2,%3}, {%4,%5,%6,%7}, {%8,%9}, {%0,%1,%2,%3};\n"
        : "+f"(d[0]), "+f"(d[1]), "+f"(d[2]), "+f"(d[3])
        : "r"(a[0]), "r"(a[1]), "r"(a[2]), "r"(a[3]), "r"(b0), "r"(b1));
}
__device__ __forceinline__ void ldsm_x4(unsigned& r0, unsigned& r1, unsigned& r2, unsigned& r3, unsigned a) {
    asm volatile("ldmatrix.sync.aligned.m8n8.x4.shared.b16 {%0,%1,%2,%3}, [%4];\n"
                 : "=r"(r0), "=r"(r1), "=r"(r2), "=r"(r3) : "r"(a));
}
__device__ __forceinline__ void ldsm_x4t(unsigned& r0, unsigned& r1, unsigned& r2, unsigned& r3, unsigned a) {
    asm volatile("ldmatrix.sync.aligned.m8n8.x4.trans.shared.b16 {%0,%1,%2,%3}, [%4];\n"
                 : "=r"(r0), "=r"(r1), "=r"(r2), "=r"(r3) : "r"(a));
}
__device__ __forceinline__ void cp_async16(unsigned dst, const void* src) {
    asm volatile("cp.async.cg.shared.global [%0], [%1], 16;\n" :: "r"(dst), "l"(src));
}
__device__ __forceinline__ void cp_commit() { asm volatile("cp.async.commit_group;\n" ::: "memory"); }
template<int N> __device__ __forceinline__ void cp_wait() {
    asm volatile("cp.async.wait_group %0;\n" :: "n"(N) : "memory");
}
__device__ __forceinline__ unsigned pack2(__half a, __half b) {
    __half2 h = __halves2half2(a, b);
    return *reinterpret_cast<unsigned*>(&h);
}

// ---------------- x split (fp32 -> hi/lo halves) + fused RoPE table ----------------
__global__ void k_split_x(const float* __restrict__ src, int n4) {
    int i = blockIdx.x * blockDim.x + threadIdx.x;
    if (blockIdx.x < 256) {
        int idx = blockIdx.x * 256 + threadIdx.x;   // < 65536 = L_*32
        int l = idx >> 5, f = idx & 31;
        double invd = pow(10000.0, -(double)(2 * f) / 64.0);
        float invf = (float)invd;        // fp32 inv_freq matches jax value
        float ang = (float)l * invf;     // fp32 angle matches reference rounding
        double da = (double)ang;
        g_cos[idx] = (float)cos(da);
        g_sin[idx] = (float)sin(da);
    }
    if (i >= n4) return;
    float4 v = reinterpret_cast<const float4*>(src)[i];
    __half h0 = __float2half(v.x), h1 = __float2half(v.y);
    __half h2 = __float2half(v.z), h3 = __float2half(v.w);
    __half l0 = __float2half(v.x - __half2float(h0));
    __half l1 = __float2half(v.y - __half2float(h1));
    __half l2 = __float2half(v.z - __half2float(h2));
    __half l3 = __float2half(v.w - __half2float(h3));
    reinterpret_cast<__half2*>(g_xh)[2 * i]     = __halves2half2(h0, h1);
    reinterpret_cast<__half2*>(g_xh)[2 * i + 1] = __halves2half2(h2, h3);
    reinterpret_cast<__half2*>(g_xl)[2 * i]     = __halves2half2(l0, l1);
    reinterpret_cast<__half2*>(g_xl)[2 * i + 1] = __halves2half2(l2, l3);
}

// ---------------- weight split (keeps [K][N] layout) ----------------
__global__ void k_split_w(const float* __restrict__ src, int which, int n4) {
    __half* hi = (which == 1) ? g_wqh : g_woh;
    __half* lo = (which == 1) ? g_wql : g_wol;
    int i = blockIdx.x * blockDim.x + threadIdx.x;
    if (i >= n4) return;
    float4 v = reinterpret_cast<const float4*>(src)[i];
    __half h0 = __float2half(v.x), h1 = __float2half(v.y);
    __half h2 = __float2half(v.z), h3 = __float2half(v.w);
    __half l0 = __float2half(v.x - __half2float(h0));
    __half l1 = __float2half(v.y - __half2float(h1));
    __half l2 = __float2half(v.z - __half2float(h2));
    __half l3 = __float2half(v.w - __half2float(h3));
    reinterpret_cast<__half2*>(hi)[2 * i]     = __halves2half2(h0, h1);
    reinterpret_cast<__half2*>(hi)[2 * i + 1] = __halves2half2(h2, h3);
    reinterpret_cast<__half2*>(lo)[2 * i]     = __halves2half2(l0, l1);
    reinterpret_cast<__half2*>(lo)[2 * i + 1] = __halves2half2(l2, l3);
}

// ---------------- split-fp16 raw-mma GEMM, 512 threads, 256x128 tile, 3-stage ----------------
// which==0: A=x(split), B=Wqkv(split), fused epilogue: bias+rmsnorm+rope+split -> g_{q,k,v}_{hi,lo}
// which==1: A=attn_out(split), B=Wout(split), epilogue: bias -> Cext fp32
#define GA_LD 40
#define GB_LD 136
#define G_AL (256 * GA_LD)              // 10240 halfs
#define G_BH (2 * 256 * GA_LD)          // 20480
#define G_BLo (G_BH + 32 * GB_LD)       // 24832
#define G_STAGE (G_BH + 2 * 32 * GB_LD) // 29184 halfs per stage
#define GEMM_SMEM (3 * G_STAGE * 2)     // 175104 bytes (epilogue staging reuses this)

__device__ __forceinline__ void gemm_load_stage(unsigned smb, int s,
        const __half* Ah, const __half* Al, const __half* Bh, const __half* Bl,
        int m0, int n0, int k0, int N, int K, int tid) {
    unsigned sb = smb + (unsigned)(s * (G_STAGE * 2));
#pragma unroll
    for (int t = 0; t < 2; t++) {
        int c = tid + t * 512;              // 0..1023 chunks of A per array
        int ar = c >> 2, ac = (c & 3) * 8;
        unsigned da = sb + (unsigned)((ar * GA_LD + ac) * 2);
        cp_async16(da, Ah + (size_t)(m0 + ar) * K + k0 + ac);
        cp_async16(da + (unsigned)(G_AL * 2), Al + (size_t)(m0 + ar) * K + k0 + ac);
    }
    {
        int br = tid >> 4, bc = (tid & 15) * 8;   // 512 chunks of B per array
        unsigned db = sb + (unsigned)((G_BH + br * GB_LD + bc) * 2);
        cp_async16(db, Bh + (size_t)(k0 + br) * N + n0 + bc);
        cp_async16(db + (unsigned)((G_BLo - G_BH) * 2), Bl + (size_t)(k0 + br) * N + n0 + bc);
    }
}

__global__ __launch_bounds__(512, 1) void k_gemm(int which, const float* __restrict__ bias,
                                                 const float* __restrict__ qn_w,
                                                 const float* __restrict__ kn_w,
                                                 float* __restrict__ Cext,
                                                 int M, int N, int K) {
    extern __shared__ __align__(128) char sm_[];
    unsigned smb = (unsigned)__cvta_generic_to_shared(sm_);

    const __half* Ah = which ? g_aoh : g_xh;
    const __half* Al = which ? g_aol : g_xl;
    const __half* Bh = which ? g_woh : g_wqh;
    const __half* Bl = which ? g_wol : g_wql;

    int tid = threadIdx.x;
    int m0 = blockIdx.y * 256, n0 = blockIdx.x * 128;
    int wid = tid >> 5, lane = tid & 31;
    int wm = wid & 7, wn = wid >> 3;   // 8x2 warp grid; warp tile 32 rows x 64 cols

    float acc[2][8][4];                // [m16-tile][n8-tile][c-frag]
#pragma unroll
    for (int mi = 0; mi < 2; mi++)
#pragma unroll
        for (int g = 0; g < 8; g++)
#pragma unroll
            for (int r = 0; r < 4; r++) acc[mi][g][r] = 0.0f;

    gemm_load_stage(smb, 0, Ah, Al, Bh, Bl, m0, n0, 0,  N, K, tid); cp_commit();
    gemm_load_stage(smb, 1, Ah, Al, Bh, Bl, m0, n0, 32, N, K, tid); cp_commit();

    // ldmatrix lane addressing (constant per thread)
    int a_rofs = ((lane >> 3) & 1) * 8 + (lane & 7);   // row-within-16 provider
    int a_cofs = (lane >> 4) * 8;                      // k offset provider
    int b_rofs = ((lane >> 3) & 1) * 8 + (lane & 7);
    int b_cofs = ((lane >> 4) << 3);

    int niter = K / 32;
    for (int it = 0; it < niter; it++) {
        if (it < niter - 1) cp_wait<1>(); else cp_wait<0>();
        __syncthreads();
        int s = it - (it / 3) * 3;
        unsigned sb = smb + (unsigned)(s * (G_STAGE * 2));

#pragma unroll
        for (int kk = 0; kk < 32; kk += 16) {
            // A fragments: 2 m16-tiles, hi & lo
            unsigned ah[2][4], al[2][4];
#pragma unroll
            for (int mi = 0; mi < 2; mi++) {
                unsigned aaddr = sb + (unsigned)(((wm * 32 + mi * 16 + a_rofs) * GA_LD
                                                 + kk + a_cofs) * 2);
                ldsm_x4(ah[mi][0], ah[mi][1], ah[mi][2], ah[mi][3], aaddr);
                ldsm_x4(al[mi][0], al[mi][1], al[mi][2], al[mi][3],
                        aaddr + (unsigned)(G_AL * 2));
            }
            // B: 4 groups of n16, trans-ldmatrix from [k][n]
#pragma unroll
            for (int g = 0; g < 4; g++) {
                unsigned baddr = sb + (unsigned)((G_BH + (kk + b_rofs) * GB_LD
                                                  + wn * 64 + g * 16 + b_cofs) * 2);
                unsigned bh0, bh1, bh2, bh3, bl0, bl1, bl2, bl3;
                ldsm_x4t(bh0, bh1, bh2, bh3, baddr);
                ldsm_x4t(bl0, bl1, bl2, bl3, baddr + (unsigned)((G_BLo - G_BH) * 2));
#pragma unroll
                for (int mi = 0; mi < 2; mi++) {
                    mma_fp16(acc[mi][2 * g],     ah[mi], bh0, bh1);
                    mma_fp16(acc[mi][2 * g],     al[mi], bh0, bh1);
                    mma_fp16(acc[mi][2 * g],     ah[mi], bl0, bl1);
                    mma_fp16(acc[mi][2 * g + 1], ah[mi], bh2, bh3);
                    mma_fp16(acc[mi][2 * g + 1], al[mi], bh2, bh3);
                    mma_fp16(acc[mi][2 * g + 1], ah[mi], bl2, bl3);
                }
            }
        }
        if (it + 2 < niter) {
            int s2 = (it + 2) - ((it + 2) / 3) * 3;
            gemm_load_stage(smb, s2, Ah, Al, Bh, Bl, m0, n0, (it + 2) * 32, N, K, tid);
            cp_commit();
        }
    }

    // ---- epilogue: stage warp tile (32x64) to smem, one lane per row ----
    __syncthreads();                       // pipeline smem free for staging
    float* st = (float*)sm_ + (size_t)wid * (32 * 68);
    {
        int cr = lane >> 2, cc = (lane & 3) * 2;
#pragma unroll
        for (int mi = 0; mi < 2; mi++)
#pragma unroll
            for (int g = 0; g < 8; g++) {
                st[(mi * 16 + cr) * 68 + g * 8 + cc]     = acc[mi][g][0];
                st[(mi * 16 + cr) * 68 + g * 8 + cc + 1] = acc[mi][g][1];
                st[(mi * 16 + cr + 8) * 68 + g * 8 + cc]     = acc[mi][g][2];
                st[(mi * 16 + cr + 8) * 68 + g * 8 + cc + 1] = acc[mi][g][3];
            }
    }
    __syncwarp();

    int gr = m0 + wm * 32 + lane;          // global row (lane owns one row)
    int gn0 = n0 + wn * 64;                // global col base (64-aligned => single head/matrix)
    float* rp = st + lane * 68;

    if (which == 0) {
        int sel = gn0 >> 10;               // 0=Q, 1=K, 2=V
        int h = (gn0 & 1023) >> 6;
        int b = gr >> 11, l = gr & 2047;
        size_t dst = ((size_t)(b * 16 + h) * 2048 + l) * 64;
        __half *hi, *lo;
        if (sel == 0)      { hi = g_q_hi; lo = g_q_lo; }
        else if (sel == 1) { hi = g_k_hi; lo = g_k_lo; }
        else               { hi = g_v_hi; lo = g_v_lo; }

        if (sel == 2) {
#pragma unroll
            for (int c = 0; c < 64; c += 2) {
                float v0 = rp[c]     + bias[gn0 + c];
                float v1 = rp[c + 1] + bias[gn0 + c + 1];
                __half a0 = __float2half(v0), a1 = __float2half(v1);
                *(unsigned*)(hi + dst + c) = pack2(a0, a1);
                *(unsigned*)(lo + dst + c) = pack2(__float2half(v0 - __half2float(a0)),
                                                   __float2half(v1 - __half2float(a1)));
            }
        } else {
            const float* w = (sel == 0) ? qn_w : kn_w;
            float ss = 0.f;
#pragma unroll
            for (int c = 0; c < 64; c++) {
                float v = rp[c] + bias[gn0 + c];
                rp[c] = v;
                ss += v * v;
            }
            float rms = rsqrtf(ss * (1.0f / 64.0f) + 1e-6f);
            float qs = (sel == 0) ? 0.125f : 1.0f;   // fold attn scale into Q
#pragma unroll
            for (int c = 0; c < 32; c += 2) {
                float cv0 = g_cos[l * 32 + c],     sv0 = g_sin[l * 32 + c];
                float cv1 = g_cos[l * 32 + c + 1], sv1 = g_sin[l * 32 + c + 1];
                float t10 = rp[c]      * rms * w[c];
                float t11 = rp[c + 1]  * rms * w[c + 1];
                float t20 = rp[c + 32] * rms * w[c + 32];
                float t21 = rp[c + 33] * rms * w[c + 33];
                float o10 = (t10 * cv0 - t20 * sv0) * qs;
                float o11 = (t11 * cv1 - t21 * sv1) * qs;
                float o20 = (t10 * sv0 + t20 * cv0) * qs;
                float o21 = (t11 * sv1 + t21 * cv1) * qs;
                __half a0 = __float2half(o10), a1 = __float2half(o11);
                __half b0 = __float2half(o20), b1 = __float2half(o21);
                *(unsigned*)(hi + dst + c)      = pack2(a0, a1);
                *(unsigned*)(hi + dst + 32 + c) = pack2(b0, b1);
                *(unsigned*)(lo + dst + c)      = pack2(__float2half(o10 - __half2float(a0)),
                                                        __float2half(o11 - __half2float(a1)));
                *(unsigned*)(lo + dst + 32 + c) = pack2(__float2half(o20 - __half2float(b0)),
                                                        __float2half(o21 - __half2float(b1)));
            }
        }
    } else {
        float* dst = Cext + (size_t)gr * N + gn0;
#pragma unroll
        for (int c = 0; c < 64; c += 4) {
            float4 v;
            v.x = rp[c]     + bias[gn0 + c];
            v.y = rp[c + 1] + bias[gn0 + c + 1];
            v.z = rp[c + 2] + bias[gn0 + c + 2];
            v.w = rp[c + 3] + bias[gn0 + c + 3];
            *reinterpret_cast<float4*>(dst + c) = v;
        }
    }
}

// ---------------- FA2-style flash attention, register-resident, 3-stage cp.async ----------------
#define ATT_LD 72
#define ATT_TILE (64 * ATT_LD)
#define ATT_STAGE (4 * ATT_TILE)
#define ATT_SMEM (3 * ATT_STAGE * 2)

__device__ __forceinline__ void att_load_tile(unsigned smb, size_t gbase, int j, int s, int tid) {
    const __half* src0 = g_k_hi + gbase;
    const __half* src1 = g_k_lo + gbase;
    const __half* src2 = g_v_hi + gbase;
    const __half* src3 = g_v_lo + gbase;
#pragma unroll
    for (int t = 0; t < 2; t++) {
        int c = tid + t * 256;
        int row = c >> 3, col = (c & 7) * 8;
        size_t goff = (size_t)(j * 64 + row) * 64 + col;
        unsigned d = smb + (unsigned)((s * ATT_STAGE + row * ATT_LD + col) * 2);
        cp_async16(d,                                src0 + goff);
        cp_async16(d + (unsigned)(ATT_TILE * 2),     src1 + goff);
        cp_async16(d + (unsigned)(2 * ATT_TILE * 2), src2 + goff);
        cp_async16(d + (unsigned)(3 * ATT_TILE * 2), src3 + goff);
    }
}

__global__ __launch_bounds__(256, 1) void k_attn() {
    extern __shared__ __align__(128) char sm_[];
    unsigned smb = (unsigned)__cvta_generic_to_shared(sm_);

    int tid = threadIdx.x, lane = tid & 31, wid = tid >> 5;
    int bh = blockIdx.y;
    size_t gbase = (size_t)bh * (2048 * 64);
    int q0 = blockIdx.x * 128 + wid * 16;

    unsigned qf[2][4][4];
    {
        const __half* Qh = g_q_hi + gbase;
        const __half* Ql = g_q_lo + gbase;
        int r0 = q0 + (lane >> 2);
        int cb = (lane & 3) * 2;
#pragma unroll
        for (int kk = 0; kk < 4; kk++) {
            int c = kk * 16 + cb;
            qf[0][kk][0] = *(const unsigned*)(Qh + (size_t)r0 * 64 + c);
            qf[0][kk][1] = *(const unsigned*)(Qh + (size_t)(r0 + 8) * 64 + c);
            qf[0][kk][2] = *(const unsigned*)(Qh + (size_t)r0 * 64 + c + 8);
            qf[0][kk][3] = *(const unsigned*)(Qh + (size_t)(r0 + 8) * 64 + c + 8);
            qf[1][kk][0] = *(const unsigned*)(Ql + (size_t)r0 * 64 + c);
            qf[1][kk][1] = *(const unsigned*)(Ql + (size_t)(r0 + 8) * 64 + c);
            qf[1][kk][2] = *(const unsigned*)(Ql + (size_t)r0 * 64 + c + 8);
            qf[1][kk][3] = *(const unsigned*)(Ql + (size_t)(r0 + 8) * 64 + c + 8);
        }
    }

    float oacc[8][4];
#pragma unroll
    for (int t = 0; t < 8; t++) { oacc[t][0] = 0.f; oacc[t][1] = 0.f; oacc[t][2] = 0.f; oacc[t][3] = 0.f; }
    float m0 = -1e30f, m1 = -1e30f, l0 = 0.f, l1 = 0.f;

    att_load_tile(smb, gbase, 0, 0, tid); cp_commit();
    att_load_tile(smb, gbase, 1, 1, tid); cp_commit();

    for (int j = 0; j < 32; j++) {
        int s = j - (j / 3) * 3;
        if (j < 31) cp_wait<1>(); else cp_wait<0>();
        __syncthreads();

        unsigned kbase = smb + (unsigned)(s * ATT_STAGE * 2);
        unsigned vbase = kbase + (unsigned)(2 * ATT_TILE * 2);

        float sacc[8][4];
#pragma unroll
        for (int t = 0; t < 8; t++) { sacc[t][0] = 0.f; sacc[t][1] = 0.f; sacc[t][2] = 0.f; sacc[t][3] = 0.f; }
#pragma unroll
        for (int kk = 0; kk < 4; kk++) {
#pragma unroll
            for (int p = 0; p < 4; p++) {
                int row = p * 16 + ((lane >> 4) << 3) + (lane & 7);
                int col = kk * 16 + ((lane >> 3) & 1) * 8;
                unsigned addr = kbase + (unsigned)((row * ATT_LD + col) * 2);
                unsigned kh0, kh1, kh2, kh3, kl0, kl1, kl2, kl3;
                ldsm_x4(kh0, kh1, kh2, kh3, addr);
                ldsm_x4(kl0, kl1, kl2, kl3, addr + (unsigned)(ATT_TILE * 2));
                mma_fp16(sacc[2 * p],     qf[0][kk], kh0, kh1);
                mma_fp16(sacc[2 * p],     qf[1][kk], kh0, kh1);
                mma_fp16(sacc[2 * p],     qf[0][kk], kl0, kl1);
                mma_fp16(sacc[2 * p + 1], qf[0][kk], kh2, kh3);
                mma_fp16(sacc[2 * p + 1], qf[1][kk], kh2, kh3);
                mma_fp16(sacc[2 * p + 1], qf[0][kk], kl2, kl3);
            }
        }

        float mx0 = -1e30f, mx1 = -1e30f;
#pragma unroll
        for (int t = 0; t < 8; t++) {
            mx0 = fmaxf(mx0, fmaxf(sacc[t][0], sacc[t][1]));
            mx1 = fmaxf(mx1, fmaxf(sacc[t][2], sacc[t][3]));
        }
        mx0 = fmaxf(mx0, __shfl_xor_sync(0xffffffffu, mx0, 1));
        mx0 = fmaxf(mx0, __shfl_xor_sync(0xffffffffu, mx0, 2));
        mx1 = fmaxf(mx1, __shfl_xor_sync(0xffffffffu, mx1, 1));
        mx1 = fmaxf(mx1, __shfl_xor_sync(0xffffffffu, mx1, 2));
        float mn0 = fmaxf(m0, mx0), mn1 = fmaxf(m1, mx1);
        float c0 = __expf(m0 - mn0), c1 = __expf(m1 - mn1);
        m0 = mn0; m1 = mn1;

        float ls0 = 0.f, ls1 = 0.f;
        unsigned pf[2][4][4];
#pragma unroll
        for (int p = 0; p < 4; p++) {
#pragma unroll
            for (int u = 0; u < 2; u++) {
                int t = 2 * p + u;
                float e0 = __expf(sacc[t][0] - mn0);
                float e1 = __expf(sacc[t][1] - mn0);
                float e2 = __expf(sacc[t][2] - mn1);
                float e3 = __expf(sacc[t][3] - mn1);
                ls0 += e0 + e1; ls1 += e2 + e3;
                __half h0 = __float2half_rn(e0), h1 = __float2half_rn(e1);
                __half h2 = __float2half_rn(e2), h3 = __float2half_rn(e3);
                pf[0][p][2 * u]     = pack2(h0, h1);
                pf[0][p][2 * u + 1] = pack2(h2, h3);
                pf[1][p][2 * u]     = pack2(__float2half_rn(e0 - __half2float(h0)),
                                            __float2half_rn(e1 - __half2float(h1)));
                pf[1][p][2 * u + 1] = pack2(__float2half_rn(e2 - __half2float(h2)),
                                            __float2half_rn(e3 - __half2float(h3)));
            }
        }
        ls0 += __shfl_xor_sync(0xffffffffu, ls0, 1);
        ls0 += __shfl_xor_sync(0xffffffffu, ls0, 2);
        ls1 += __shfl_xor_sync(0xffffffffu, ls1, 1);
        ls1 += __shfl_xor_sync(0xffffffffu, ls1, 2);
        l0 = l0 * c0 + ls0;
        l1 = l1 * c1 + ls1;
#pragma unroll
        for (int t = 0; t < 8; t++) { oacc[t][0] *= c0; oacc[t][1] *= c0; oacc[t][2] *= c1; oacc[t][3] *= c1; }

#pragma unroll
        for (int kk = 0; kk < 4; kk++) {
#pragma unroll
            for (int t2 = 0; t2 < 4; t2++) {
                int row = kk * 16 + ((lane >> 3) & 1) * 8 + (lane & 7);
                int col = t2 * 16 + ((lane >> 4) << 3);
                unsigned addr = vbase + (unsigned)((row * ATT_LD + col) * 2);
                unsigned vh0, vh1, vh2, vh3, vl0, vl1, vl2, vl3;
                ldsm_x4t(vh0, vh1, vh2, vh3, addr);
                ldsm_x4t(vl0, vl1, vl2, vl3, addr + (unsigned)(ATT_TILE * 2));
                mma_fp16(oacc[2 * t2],     pf[0][kk], vh0, vh1);
                mma_fp16(oacc[2 * t2],     pf[1][kk], vh0, vh1);
                mma_fp16(oacc[2 * t2],     pf[0][kk], vl0, vl1);
                mma_fp16(oacc[2 * t2 + 1], pf[0][kk], vh2, vh3);
                mma_fp16(oacc[2 * t2 + 1], pf[1][kk], vh2, vh3);
                mma_fp16(oacc[2 * t2 + 1], pf[0][kk], vl2, vl3);
            }
        }

        if (j + 2 < 32) {
            int s2 = (j + 2) - ((j + 2) / 3) * 3;
            att_load_tile(smb, gbase, j + 2, s2, tid);
            cp_commit();
        }
    }

    float i0 = 1.0f / l0, i1 = 1.0f / l1;
    int b = bh >> 4, h = bh & 15;
    int r = q0 + (lane >> 2);
    size_t ob0 = (size_t)(b * 2048 + r) * 1024 + h * 64;
    size_t ob1 = ob0 + (size_t)8 * 1024;
#pragma unroll
    for (int t = 0; t < 8; t++) {
        int c = t * 8 + (lane & 3) * 2;
        float v0 = oacc[t][0] * i0, v1 = oacc[t][1] * i0;
        float v2 = oacc[t][2] * i1, v3 = oacc[t][3] * i1;
        __half h0 = __float2half_rn(v0), h1 = __float2half_rn(v1);
        __half h2 = __float2half_rn(v2), h3 = __float2half_rn(v3);
        *(unsigned*)(g_aoh + ob0 + c) = pack2(h0, h1);
        *(unsigned*)(g_aoh + ob1 + c) = pack2(h2, h3);
        *(unsigned*)(g_aol + ob0 + c) = pack2(__float2half_rn(v0 - __half2float(h0)),
                                              __float2half_rn(v1 - __half2float(h1)));
        *(unsigned*)(g_aol + ob1 + c) = pack2(__float2half_rn(v2 - __half2float(h2)),
                                              __float2half_rn(v3 - __half2float(h3)));
    }
}

// ---------------- host launcher ----------------
extern "C" void kernel_launch(void* const* d_in, const int* in_sizes, int n_in,
                              void* d_out, int out_size) {
    (void)in_sizes; (void)n_in; (void)out_size;
    const float* x    = (const float*)d_in[0];
    const float* Wqkv = (const float*)d_in[1];
    const float* bqkv = (const float*)d_in[2];
    const float* qn_w = (const float*)d_in[3];
    const float* kn_w = (const float*)d_in[4];
    const float* Wout = (const float*)d_in[5];
    const float* bout = (const float*)d_in[6];
    float* out = (float*)d_out;

    // [0] split x + fused RoPE table
    k_split_x<<<(MROWS * D_ / 4) / 256, 256>>>(x, MROWS * D_ / 4);
    // [1] split Wqkv
    k_split_w<<<(D_ * N3D / 4) / 256, 256>>>(Wqkv, 1, D_ * N3D / 4);

    // [2] QKV projection + fused bias/rmsnorm/rope/split epilogue
    cudaFuncSetAttribute(k_gemm, cudaFuncAttributeMaxDynamicSharedMemorySize, GEMM_SMEM);
    k_gemm<<<dim3(N3D / 128, MROWS / 256), 512, GEMM_SMEM>>>(0, bqkv, qn_w, kn_w, nullptr,
                                                             MROWS, N3D, D_);

    // [3] attention (ncu -s 5 -c 1 lands here: 2 harness launches + my index 3)
    cudaFuncSetAttribute(k_attn, cudaFuncAttributeMaxDynamicSharedMemorySize, ATT_SMEM);
    k_attn<<<dim3(L_ / 128, B_ * H_), 256, ATT_SMEM>>>();

    // [4] split Wout (independent of attention; overlaps its tail)
    k_split_w<<<(D_ * D_ / 4) / 256, 256>>>(Wout, 2, D_ * D_ / 4);

    // [5] output projection + bias -> d_out
    k_gemm<<<dim3(D_ / 128, MROWS / 256), 512, GEMM_SMEM>>>(1, bout, qn_w, kn_w, out,
                                                            MROWS, D_, D_);
}